// round 6
// baseline (speedup 1.0000x reference)
#include <cuda_runtime.h>
#include <math.h>
#include <stdint.h>

#define BATCH 16
#define HW    4096
#define CHW   1048576u

// Scratch (no allocation allowed -> __device__ globals)
__device__ float g_y[3ull * 16777216ull];   // fx, gx, hx
__device__ float g_o[16777216ull];          // attention output (tf32-rounded)
__device__ float g_xr[16777216ull];         // x, tf32-rounded
__device__ float g_wt[256 * 768];           // concat(wf,wg,wh) transposed [k][m], tf32-rounded
__device__ float g_wtv[256 * 256];          // wv transposed [k][m], tf32-rounded
__device__ float g_bcat[768];

__device__ __forceinline__ uint32_t f2tf32(float v) {   // round-to-nearest (unbiased)
    uint32_t r;
    asm("cvt.rna.tf32.f32 %0, %1;" : "=r"(r) : "f"(v));
    return r;
}
__device__ __forceinline__ float rtf(float v) { return __uint_as_float(f2tf32(v)); }

__device__ __forceinline__ void mma_tf32(float* c, const uint32_t* a, const uint32_t* b) {
    asm volatile(
        "mma.sync.aligned.m16n8k8.row.col.f32.tf32.tf32.f32 "
        "{%0,%1,%2,%3}, {%4,%5,%6,%7}, {%8,%9}, {%0,%1,%2,%3};"
        : "+f"(c[0]), "+f"(c[1]), "+f"(c[2]), "+f"(c[3])
        : "r"(a[0]), "r"(a[1]), "r"(a[2]), "r"(a[3]), "r"(b[0]), "r"(b[1]));
}

__device__ __forceinline__ void cpa16(uint32_t s, const void* g) {
    asm volatile("cp.async.cg.shared.global [%0], [%1], 16;" :: "r"(s), "l"(g));
}
#define CP_COMMIT()  asm volatile("cp.async.commit_group;" ::: "memory")
#define CP_WAIT2()   asm volatile("cp.async.wait_group 2;" ::: "memory")

// ---------------------------------------------------------------------------
// Prep: transpose weights to k-major + tf32-round, concat f/g/h, concat biases.
// ---------------------------------------------------------------------------
__global__ void prep_kernel(const float* __restrict__ wf, const float* __restrict__ wg,
                            const float* __restrict__ wh, const float* __restrict__ wv,
                            const float* __restrict__ bf, const float* __restrict__ bg,
                            const float* __restrict__ bh) {
    int idx = blockIdx.x * 256 + threadIdx.x;   // < 196608
    int m = idx >> 8, k = idx & 255;
    const float* w = (m < 256) ? wf : (m < 512) ? wg : wh;
    g_wt[k * 768 + m] = rtf(w[(m & 255) * 256 + k]);
    if (idx < 65536) g_wtv[k * 256 + m] = rtf(wv[idx]);   // idx = m*256+k
    if (idx < 256) {
        g_bcat[idx]       = bf[idx];
        g_bcat[256 + idx] = bg[idx];
        g_bcat[512 + idx] = bh[idx];
    }
}

// Round x to tf32 once (so the conv B-tiles can be cp.async'd without cvt).
__global__ void round_x_kernel(const float* __restrict__ x) {
    size_t i = ((size_t)blockIdx.x * 256 + threadIdx.x) * 4;
    float4 v = *(const float4*)&x[i];
    v.x = rtf(v.x); v.y = rtf(v.y); v.z = rtf(v.z); v.w = rtf(v.w);
    *(float4*)&g_xr[i] = v;
}

// ---------------------------------------------------------------------------
// HMMA tf32 conv GEMM (unchanged from round 5)
// ---------------------------------------------------------------------------
#define SSTRIDE 136
#define SA_OFF(buf, k) ((((buf) * 2 + 0) * 16 + (k)) * SSTRIDE)
#define SB_OFF(buf, k) ((((buf) * 2 + 1) * 16 + (k)) * SSTRIDE)
#define CONV_SMEM (4 * 2 * 16 * SSTRIDE * 4)   // 69632

__global__ __launch_bounds__(256, 2)
void conv_hmma_kernel(const float* __restrict__ X0, const float* __restrict__ WT,
                      const float* __restrict__ bias, float* __restrict__ Y,
                      int wstride) {
    extern __shared__ uint32_t dsm[];

    const int tid  = threadIdx.x;
    const int lane = tid & 31;
    const int warp = tid >> 5;
    const int mw   = warp >> 2;
    const int nw   = warp & 3;
    const int b    = blockIdx.z;
    const int n0   = blockIdx.x * 128;
    const int m0   = blockIdx.y * 128;
    const float* X = X0 + (size_t)b * CHW;

    const int lrow = tid >> 5;
    const int lcol = (tid & 31) << 2;
    const float* gA = WT + (size_t)lrow * wstride + m0 + lcol;
    const float* gB = X  + (size_t)lrow * HW + n0 + lcol;
    const uint32_t sbase = (uint32_t)__cvta_generic_to_shared(dsm);

    float acc[4][4][4];
#pragma unroll
    for (int i = 0; i < 4; i++)
#pragma unroll
        for (int j = 0; j < 4; j++)
#pragma unroll
            for (int r = 0; r < 4; r++) acc[i][j][r] = 0.f;

#pragma unroll
    for (int s = 0; s < 3; s++) {
        const int buf = s;
#pragma unroll
        for (int h = 0; h < 2; h++) {
            cpa16(sbase + (SA_OFF(buf, lrow + h * 8) + lcol) * 4,
                  gA + (size_t)(s * 16 + h * 8) * wstride);
            cpa16(sbase + (SB_OFF(buf, lrow + h * 8) + lcol) * 4,
                  gB + (size_t)(s * 16 + h * 8) * HW);
        }
        CP_COMMIT();
    }

    for (int kt = 0; kt < 16; kt++) {
        const int buf = kt & 3;
        CP_WAIT2();
        __syncthreads();

        if (kt < 13) {
            const int s = kt + 3, nb = s & 3;
#pragma unroll
            for (int h = 0; h < 2; h++) {
                cpa16(sbase + (SA_OFF(nb, lrow + h * 8) + lcol) * 4,
                      gA + (size_t)(s * 16 + h * 8) * wstride);
                cpa16(sbase + (SB_OFF(nb, lrow + h * 8) + lcol) * 4,
                      gB + (size_t)(s * 16 + h * 8) * HW);
            }
        }
        CP_COMMIT();

        const uint32_t* A0 = dsm + SA_OFF(buf, 0) + (lane & 3) * SSTRIDE
                                 + mw * 64 + (lane >> 2);
        const uint32_t* B0 = dsm + SB_OFF(buf, 0) + (lane & 3) * SSTRIDE
                                 + nw * 32 + (lane >> 2);
#pragma unroll
        for (int kk = 0; kk < 16; kk += 8) {
            const uint32_t* Ak = A0 + kk * SSTRIDE;
            const uint32_t* Bk = B0 + kk * SSTRIDE;
            uint32_t af[4][4];
#pragma unroll
            for (int mi = 0; mi < 4; mi++) {
                af[mi][0] = Ak[mi * 16];
                af[mi][1] = Ak[mi * 16 + 8];
                af[mi][2] = Ak[4 * SSTRIDE + mi * 16];
                af[mi][3] = Ak[4 * SSTRIDE + mi * 16 + 8];
            }
            uint32_t bfr[4][2];
#pragma unroll
            for (int nj = 0; nj < 4; nj++) {
                bfr[nj][0] = Bk[nj * 8];
                bfr[nj][1] = Bk[4 * SSTRIDE + nj * 8];
            }
#pragma unroll
            for (int mi = 0; mi < 4; mi++)
#pragma unroll
                for (int nj = 0; nj < 4; nj++)
                    mma_tf32(acc[mi][nj], af[mi], bfr[nj]);
        }
        __syncthreads();
    }

#pragma unroll
    for (int mi = 0; mi < 4; mi++) {
        int mr0 = m0 + mw * 64 + mi * 16 + (lane >> 2);
        float bv0 = bias[mr0];
        float bv1 = bias[mr0 + 8];
        float* y0 = Y + ((size_t)(mr0 >> 8) * BATCH + b) * CHW + (size_t)(mr0 & 255) * HW + n0;
        int mr1 = mr0 + 8;
        float* y1 = Y + ((size_t)(mr1 >> 8) * BATCH + b) * CHW + (size_t)(mr1 & 255) * HW + n0;
#pragma unroll
        for (int nj = 0; nj < 4; nj++) {
            int nc = nw * 32 + nj * 8 + 2 * (lane & 3);
            float2 v0 = make_float2(acc[mi][nj][0] + bv0, acc[mi][nj][1] + bv0);
            float2 v1 = make_float2(acc[mi][nj][2] + bv1, acc[mi][nj][3] + bv1);
            *(float2*)(y0 + nc) = v0;
            *(float2*)(y1 + nc) = v1;
        }
    }
}

// ---------------------------------------------------------------------------
// Fused attention, one CTA per (b,c), 128 threads (4 warps), all-HMMA:
//   GEMM1 (scores) via tf32x3 split (hi/lo) -> ~fp32-exact scores
//   softmax in accumulator fragments (row fully inside one warp; shfl_xor 1,2)
//   GEMM2 (O^T = attn^T Hm^T) via single-pass tf32
// smem (dynamic, 73728 B):
//   Fh [64][72] @0, Fl @4608, Gh @9216, Gl @13824   (floats)
//   after GEMM1: Hm [64][68] @0, attn [64][72] @4608
// Bank exactness: stride72 transposed reads -> bank 8(lane&3)+(lane>>2);
//                 stride68 natural reads   -> bank 4(lane>>2)+(lane&3).
// ---------------------------------------------------------------------------
#define ATT_SMEM 73728

__global__ __launch_bounds__(128)
void attn_kernel(const float* __restrict__ y, float* __restrict__ o) {
    extern __shared__ float smp[];
    const int bc = blockIdx.x;
    const size_t BCHW = (size_t)BATCH * CHW;
    const float* F  = y + (size_t)bc * HW;
    const float* G  = y + BCHW + (size_t)bc * HW;
    const float* Hm = y + 2 * BCHW + (size_t)bc * HW;

    float* sFh = smp;
    float* sFl = smp + 4608;
    float* sGh = smp + 9216;
    float* sGl = smp + 13824;

    const int tid  = threadIdx.x;
    const int lane = tid & 31;
    const int warp = tid >> 5;
    const int qr   = lane >> 2;   // 0..7
    const int qc   = lane & 3;    // 0..3

    // load F,G with hi/lo tf32 split
    for (int i = tid * 4; i < 4096; i += 512) {
        float4 f = *(const float4*)&F[i];
        float4 g = *(const float4*)&G[i];
        int off = (i >> 6) * 72 + (i & 63);
        float4 fh, fl, gh, gl;
        fh.x = rtf(f.x); fl.x = rtf(f.x - fh.x);
        fh.y = rtf(f.y); fl.y = rtf(f.y - fh.y);
        fh.z = rtf(f.z); fl.z = rtf(f.z - fh.z);
        fh.w = rtf(f.w); fl.w = rtf(f.w - fh.w);
        gh.x = rtf(g.x); gl.x = rtf(g.x - gh.x);
        gh.y = rtf(g.y); gl.y = rtf(g.y - gh.y);
        gh.z = rtf(g.z); gl.z = rtf(g.z - gh.z);
        gh.w = rtf(g.w); gl.w = rtf(g.w - gh.w);
        *(float4*)&sFh[off] = fh;
        *(float4*)&sFl[off] = fl;
        *(float4*)&sGh[off] = gh;
        *(float4*)&sGl[off] = gl;
    }
    __syncthreads();

    // GEMM1 (tf32x3): S[wr][v] = sum_h F[h][wr] * G[h][v]
    // warp owns S rows [16*warp, 16*warp+16); acc[nj] covers n-tile nj (8 cols)
    float acc[8][4];
#pragma unroll
    for (int nj = 0; nj < 8; nj++)
#pragma unroll
        for (int r = 0; r < 4; r++) acc[nj][r] = 0.f;

#pragma unroll
    for (int k0 = 0; k0 < 64; k0 += 8) {
        const int h0 = k0 + qc;
        const int wr = warp * 16 + qr;
        uint32_t Ah[4], Al[4];
        Ah[0] = __float_as_uint(sFh[h0 * 72 + wr]);
        Ah[1] = __float_as_uint(sFh[h0 * 72 + wr + 8]);
        Ah[2] = __float_as_uint(sFh[(h0 + 4) * 72 + wr]);
        Ah[3] = __float_as_uint(sFh[(h0 + 4) * 72 + wr + 8]);
        Al[0] = __float_as_uint(sFl[h0 * 72 + wr]);
        Al[1] = __float_as_uint(sFl[h0 * 72 + wr + 8]);
        Al[2] = __float_as_uint(sFl[(h0 + 4) * 72 + wr]);
        Al[3] = __float_as_uint(sFl[(h0 + 4) * 72 + wr + 8]);
#pragma unroll
        for (int nj = 0; nj < 8; nj++) {
            const int v0 = nj * 8 + qr;
            uint32_t Bh[2], Bl[2];
            Bh[0] = __float_as_uint(sGh[h0 * 72 + v0]);
            Bh[1] = __float_as_uint(sGh[(h0 + 4) * 72 + v0]);
            Bl[0] = __float_as_uint(sGl[h0 * 72 + v0]);
            Bl[1] = __float_as_uint(sGl[(h0 + 4) * 72 + v0]);
            mma_tf32(acc[nj], Ah, Bh);
            mma_tf32(acc[nj], Ah, Bl);
            mma_tf32(acc[nj], Al, Bh);
        }
    }

    // softmax over v: thread holds rows (16w+qr) [c0,c1] and (16w+qr+8) [c2,c3];
    // full row spread over the 4 lanes sharing qr -> shfl_xor 1,2
    float mlo = -1e30f, mhi = -1e30f;
#pragma unroll
    for (int nj = 0; nj < 8; nj++) {
        mlo = fmaxf(mlo, fmaxf(acc[nj][0], acc[nj][1]));
        mhi = fmaxf(mhi, fmaxf(acc[nj][2], acc[nj][3]));
    }
    mlo = fmaxf(mlo, __shfl_xor_sync(0xffffffffu, mlo, 1));
    mlo = fmaxf(mlo, __shfl_xor_sync(0xffffffffu, mlo, 2));
    mhi = fmaxf(mhi, __shfl_xor_sync(0xffffffffu, mhi, 1));
    mhi = fmaxf(mhi, __shfl_xor_sync(0xffffffffu, mhi, 2));
    float slo = 0.f, shi = 0.f;
#pragma unroll
    for (int nj = 0; nj < 8; nj++) {
        acc[nj][0] = __expf(acc[nj][0] - mlo);
        acc[nj][1] = __expf(acc[nj][1] - mlo);
        acc[nj][2] = __expf(acc[nj][2] - mhi);
        acc[nj][3] = __expf(acc[nj][3] - mhi);
        slo += acc[nj][0] + acc[nj][1];
        shi += acc[nj][2] + acc[nj][3];
    }
    slo += __shfl_xor_sync(0xffffffffu, slo, 1);
    slo += __shfl_xor_sync(0xffffffffu, slo, 2);
    shi += __shfl_xor_sync(0xffffffffu, shi, 1);
    shi += __shfl_xor_sync(0xffffffffu, shi, 2);
    const float ilo = 1.0f / slo, ihi = 1.0f / shi;

    __syncthreads();   // all warps done reading F/G buffers

    // stage tf32 attn into sAt[w][v] (stride 72) and tf32 Hm into sHm[h][w] (stride 68)
    float* sHm = smp;          // overlays Fh
    float* sAt = smp + 4608;   // overlays Fl
    {
        const int wlo = warp * 16 + qr, whi = wlo + 8;
#pragma unroll
        for (int nj = 0; nj < 8; nj++) {
            const int v = nj * 8 + 2 * qc;
            float2 lo = make_float2(rtf(acc[nj][0] * ilo), rtf(acc[nj][1] * ilo));
            float2 hi = make_float2(rtf(acc[nj][2] * ihi), rtf(acc[nj][3] * ihi));
            *(float2*)&sAt[wlo * 72 + v] = lo;
            *(float2*)&sAt[whi * 72 + v] = hi;
        }
    }
    for (int i = tid * 4; i < 4096; i += 512) {
        float4 v = *(const float4*)&Hm[i];
        v.x = rtf(v.x); v.y = rtf(v.y); v.z = rtf(v.z); v.w = rtf(v.w);
        *(float4*)&sHm[(i >> 6) * 68 + (i & 63)] = v;
    }
    __syncthreads();

    // GEMM2 (tf32): C[v][h] = sum_w attn[w][v] * Hm[h][w]  (= O^T)
#pragma unroll
    for (int nj = 0; nj < 8; nj++)
#pragma unroll
        for (int r = 0; r < 4; r++) acc[nj][r] = 0.f;

#pragma unroll
    for (int k0 = 0; k0 < 64; k0 += 8) {
        const int w0 = k0 + qc;
        const int vv = warp * 16 + qr;
        uint32_t af[4];
        af[0] = __float_as_uint(sAt[w0 * 72 + vv]);
        af[1] = __float_as_uint(sAt[w0 * 72 + vv + 8]);
        af[2] = __float_as_uint(sAt[(w0 + 4) * 72 + vv]);
        af[3] = __float_as_uint(sAt[(w0 + 4) * 72 + vv + 8]);
#pragma unroll
        for (int nj = 0; nj < 8; nj++) {
            const int hh = nj * 8 + qr;
            uint32_t bfr[2];
            bfr[0] = __float_as_uint(sHm[hh * 68 + w0]);
            bfr[1] = __float_as_uint(sHm[hh * 68 + w0 + 4]);
            mma_tf32(acc[nj], af, bfr);
        }
    }

    // store O[h][v] (tf32-rounded for the final conv)
    float* O = o + (size_t)bc * HW;
    const int vr = warp * 16 + qr;
#pragma unroll
    for (int nj = 0; nj < 8; nj++) {
        const int hc = nj * 8 + 2 * qc;
        O[hc * 64 + vr]           = rtf(acc[nj][0]);
        O[(hc + 1) * 64 + vr]     = rtf(acc[nj][1]);
        O[hc * 64 + vr + 8]       = rtf(acc[nj][2]);
        O[(hc + 1) * 64 + vr + 8] = rtf(acc[nj][3]);
    }
}

// ---------------------------------------------------------------------------
extern "C" void kernel_launch(void* const* d_in, const int* in_sizes, int n_in,
                              void* d_out, int out_size) {
    const float* x  = (const float*)d_in[0];
    const float* wf = (const float*)d_in[1];
    const float* bf = (const float*)d_in[2];
    const float* wg = (const float*)d_in[3];
    const float* bg = (const float*)d_in[4];
    const float* wh = (const float*)d_in[5];
    const float* bh = (const float*)d_in[6];
    const float* wv = (const float*)d_in[7];
    const float* bv = (const float*)d_in[8];

    float *yb, *ob, *xr, *wt, *wtv, *bcat;
    cudaGetSymbolAddress((void**)&yb,   g_y);
    cudaGetSymbolAddress((void**)&ob,   g_o);
    cudaGetSymbolAddress((void**)&xr,   g_xr);
    cudaGetSymbolAddress((void**)&wt,   g_wt);
    cudaGetSymbolAddress((void**)&wtv,  g_wtv);
    cudaGetSymbolAddress((void**)&bcat, g_bcat);

    cudaFuncSetAttribute(conv_hmma_kernel,
                         cudaFuncAttributeMaxDynamicSharedMemorySize, CONV_SMEM);
    cudaFuncSetAttribute(attn_kernel,
                         cudaFuncAttributeMaxDynamicSharedMemorySize, ATT_SMEM);

    // 1) weight transpose + rounding; x rounding
    prep_kernel<<<768, 256>>>(wf, wg, wh, wv, bf, bg, bh);
    round_x_kernel<<<16384, 256>>>(x);

    // 2) fused f/g/h conv: M=768 (6 tiles), N=4096 (32 tiles), B=16
    conv_hmma_kernel<<<dim3(32, 6, 16), 256, CONV_SMEM>>>(xr, wt, bcat, yb, 768);

    // 3) per-(b,c) attention
    attn_kernel<<<4096, 128, ATT_SMEM>>>(yb, ob);

    // 4) output conv: M=256 (2 tiles)
    conv_hmma_kernel<<<dim3(32, 2, 16), 256, CONV_SMEM>>>(ob, wtv, bv, (float*)d_out, 256);
}

// round 7
// speedup vs baseline: 1.1167x; 1.1167x over previous
#include <cuda_runtime.h>
#include <math.h>
#include <stdint.h>

#define BATCH 16
#define HW    4096
#define CHW   1048576u

// Scratch (no allocation allowed -> __device__ globals)
__device__ float g_y[3ull * 16777216ull];   // fx, gx, hx
__device__ float g_o[16777216ull];          // attention output (tf32-rounded)
__device__ float g_xr[16777216ull];         // x, tf32-rounded
__device__ float g_wt[256 * 768];           // concat(wf,wg,wh) transposed [k][m], tf32-rounded
__device__ float g_wtv[256 * 256];          // wv transposed [k][m], tf32-rounded
__device__ float g_bcat[768];

__device__ __forceinline__ uint32_t f2tf32(float v) {   // round-to-nearest (unbiased)
    uint32_t r;
    asm("cvt.rna.tf32.f32 %0, %1;" : "=r"(r) : "f"(v));
    return r;
}
__device__ __forceinline__ float rtf(float v) { return __uint_as_float(f2tf32(v)); }

__device__ __forceinline__ void mma_tf32(float* c, const uint32_t* a, const uint32_t* b) {
    asm volatile(
        "mma.sync.aligned.m16n8k8.row.col.f32.tf32.tf32.f32 "
        "{%0,%1,%2,%3}, {%4,%5,%6,%7}, {%8,%9}, {%0,%1,%2,%3};"
        : "+f"(c[0]), "+f"(c[1]), "+f"(c[2]), "+f"(c[3])
        : "r"(a[0]), "r"(a[1]), "r"(a[2]), "r"(a[3]), "r"(b[0]), "r"(b[1]));
}

__device__ __forceinline__ void cpa16(uint32_t s, const void* g) {
    asm volatile("cp.async.cg.shared.global [%0], [%1], 16;" :: "r"(s), "l"(g));
}
#define CP_COMMIT()  asm volatile("cp.async.commit_group;" ::: "memory")
#define CP_WAIT2()   asm volatile("cp.async.wait_group 2;" ::: "memory")

// ---------------------------------------------------------------------------
// Prep: transpose weights to k-major + tf32-round, concat f/g/h, concat biases.
// ---------------------------------------------------------------------------
__global__ void prep_kernel(const float* __restrict__ wf, const float* __restrict__ wg,
                            const float* __restrict__ wh, const float* __restrict__ wv,
                            const float* __restrict__ bf, const float* __restrict__ bg,
                            const float* __restrict__ bh) {
    int idx = blockIdx.x * 256 + threadIdx.x;   // < 196608
    int m = idx >> 8, k = idx & 255;
    const float* w = (m < 256) ? wf : (m < 512) ? wg : wh;
    g_wt[k * 768 + m] = rtf(w[(m & 255) * 256 + k]);
    if (idx < 65536) g_wtv[k * 256 + m] = rtf(wv[idx]);   // idx = m*256+k
    if (idx < 256) {
        g_bcat[idx]       = bf[idx];
        g_bcat[256 + idx] = bg[idx];
        g_bcat[512 + idx] = bh[idx];
    }
}

// Round x to tf32 once (so the conv B-tiles can be cp.async'd without cvt).
__global__ void round_x_kernel(const float* __restrict__ x) {
    size_t i = ((size_t)blockIdx.x * 256 + threadIdx.x) * 4;
    float4 v = *(const float4*)&x[i];
    v.x = rtf(v.x); v.y = rtf(v.y); v.z = rtf(v.z); v.w = rtf(v.w);
    *(float4*)&g_xr[i] = v;
}

// ---------------------------------------------------------------------------
// HMMA tf32 conv GEMM (unchanged)
// ---------------------------------------------------------------------------
#define SSTRIDE 136
#define SA_OFF(buf, k) ((((buf) * 2 + 0) * 16 + (k)) * SSTRIDE)
#define SB_OFF(buf, k) ((((buf) * 2 + 1) * 16 + (k)) * SSTRIDE)
#define CONV_SMEM (4 * 2 * 16 * SSTRIDE * 4)   // 69632

__global__ __launch_bounds__(256, 2)
void conv_hmma_kernel(const float* __restrict__ X0, const float* __restrict__ WT,
                      const float* __restrict__ bias, float* __restrict__ Y,
                      int wstride) {
    extern __shared__ uint32_t dsm[];

    const int tid  = threadIdx.x;
    const int lane = tid & 31;
    const int warp = tid >> 5;
    const int mw   = warp >> 2;
    const int nw   = warp & 3;
    const int b    = blockIdx.z;
    const int n0   = blockIdx.x * 128;
    const int m0   = blockIdx.y * 128;
    const float* X = X0 + (size_t)b * CHW;

    const int lrow = tid >> 5;
    const int lcol = (tid & 31) << 2;
    const float* gA = WT + (size_t)lrow * wstride + m0 + lcol;
    const float* gB = X  + (size_t)lrow * HW + n0 + lcol;
    const uint32_t sbase = (uint32_t)__cvta_generic_to_shared(dsm);

    float acc[4][4][4];
#pragma unroll
    for (int i = 0; i < 4; i++)
#pragma unroll
        for (int j = 0; j < 4; j++)
#pragma unroll
            for (int r = 0; r < 4; r++) acc[i][j][r] = 0.f;

#pragma unroll
    for (int s = 0; s < 3; s++) {
        const int buf = s;
#pragma unroll
        for (int h = 0; h < 2; h++) {
            cpa16(sbase + (SA_OFF(buf, lrow + h * 8) + lcol) * 4,
                  gA + (size_t)(s * 16 + h * 8) * wstride);
            cpa16(sbase + (SB_OFF(buf, lrow + h * 8) + lcol) * 4,
                  gB + (size_t)(s * 16 + h * 8) * HW);
        }
        CP_COMMIT();
    }

    for (int kt = 0; kt < 16; kt++) {
        const int buf = kt & 3;
        CP_WAIT2();
        __syncthreads();

        if (kt < 13) {
            const int s = kt + 3, nb = s & 3;
#pragma unroll
            for (int h = 0; h < 2; h++) {
                cpa16(sbase + (SA_OFF(nb, lrow + h * 8) + lcol) * 4,
                      gA + (size_t)(s * 16 + h * 8) * wstride);
                cpa16(sbase + (SB_OFF(nb, lrow + h * 8) + lcol) * 4,
                      gB + (size_t)(s * 16 + h * 8) * HW);
            }
        }
        CP_COMMIT();

        const uint32_t* A0 = dsm + SA_OFF(buf, 0) + (lane & 3) * SSTRIDE
                                 + mw * 64 + (lane >> 2);
        const uint32_t* B0 = dsm + SB_OFF(buf, 0) + (lane & 3) * SSTRIDE
                                 + nw * 32 + (lane >> 2);
#pragma unroll
        for (int kk = 0; kk < 16; kk += 8) {
            const uint32_t* Ak = A0 + kk * SSTRIDE;
            const uint32_t* Bk = B0 + kk * SSTRIDE;
            uint32_t af[4][4];
#pragma unroll
            for (int mi = 0; mi < 4; mi++) {
                af[mi][0] = Ak[mi * 16];
                af[mi][1] = Ak[mi * 16 + 8];
                af[mi][2] = Ak[4 * SSTRIDE + mi * 16];
                af[mi][3] = Ak[4 * SSTRIDE + mi * 16 + 8];
            }
            uint32_t bfr[4][2];
#pragma unroll
            for (int nj = 0; nj < 4; nj++) {
                bfr[nj][0] = Bk[nj * 8];
                bfr[nj][1] = Bk[4 * SSTRIDE + nj * 8];
            }
#pragma unroll
            for (int mi = 0; mi < 4; mi++)
#pragma unroll
                for (int nj = 0; nj < 4; nj++)
                    mma_tf32(acc[mi][nj], af[mi], bfr[nj]);
        }
        __syncthreads();
    }

#pragma unroll
    for (int mi = 0; mi < 4; mi++) {
        int mr0 = m0 + mw * 64 + mi * 16 + (lane >> 2);
        float bv0 = bias[mr0];
        float bv1 = bias[mr0 + 8];
        float* y0 = Y + ((size_t)(mr0 >> 8) * BATCH + b) * CHW + (size_t)(mr0 & 255) * HW + n0;
        int mr1 = mr0 + 8;
        float* y1 = Y + ((size_t)(mr1 >> 8) * BATCH + b) * CHW + (size_t)(mr1 & 255) * HW + n0;
#pragma unroll
        for (int nj = 0; nj < 4; nj++) {
            int nc = nw * 32 + nj * 8 + 2 * (lane & 3);
            float2 v0 = make_float2(acc[mi][nj][0] + bv0, acc[mi][nj][1] + bv0);
            float2 v1 = make_float2(acc[mi][nj][2] + bv1, acc[mi][nj][3] + bv1);
            *(float2*)(y0 + nc) = v0;
            *(float2*)(y1 + nc) = v1;
        }
    }
}

// ---------------------------------------------------------------------------
// Fused attention, one CTA per (b,c), 256 threads (8 warps), all-HMMA:
//   warp w -> S m-tile (w>>1) [16 rows], n-half (w&1) [32 of 64 cols]
//   GEMM1 via tf32x3 split (fp32-exact scores); split softmax with one
//   cross-warp combine through a 1KB smem buffer; GEMM2 single-pass tf32.
// smem: Fh[64][72]@0, Fl@4608, Gh@9216, Gl@13824, red[64][4]@18432 (floats)
//   after GEMM1: Hm[64][68] overlays Fh, attn[64][72] overlays Fl.
// ---------------------------------------------------------------------------
#define ATT_SMEM 74752

__global__ __launch_bounds__(256)
void attn_kernel(const float* __restrict__ y, float* __restrict__ o) {
    extern __shared__ float smp[];
    const int bc = blockIdx.x;
    const size_t BCHW = (size_t)BATCH * CHW;
    const float* F  = y + (size_t)bc * HW;
    const float* G  = y + BCHW + (size_t)bc * HW;
    const float* Hm = y + 2 * BCHW + (size_t)bc * HW;

    float* sFh = smp;
    float* sFl = smp + 4608;
    float* sGh = smp + 9216;
    float* sGl = smp + 13824;
    float* red = smp + 18432;   // [64][4] : (max0, sum0, max1, sum1) per row

    const int tid  = threadIdx.x;
    const int lane = tid & 31;
    const int warp = tid >> 5;       // 0..7
    const int mt   = warp >> 1;      // S m-tile (16 rows)
    const int nh   = warp & 1;       // n-half (32 cols)
    const int qr   = lane >> 2;      // 0..7
    const int qc   = lane & 3;       // 0..3

    // load F,G with hi/lo tf32 split
    for (int i = tid * 4; i < 4096; i += 1024) {
        float4 f = *(const float4*)&F[i];
        float4 g = *(const float4*)&G[i];
        int off = (i >> 6) * 72 + (i & 63);
        float4 fh, fl, gh, gl;
        fh.x = rtf(f.x); fl.x = rtf(f.x - fh.x);
        fh.y = rtf(f.y); fl.y = rtf(f.y - fh.y);
        fh.z = rtf(f.z); fl.z = rtf(f.z - fh.z);
        fh.w = rtf(f.w); fl.w = rtf(f.w - fh.w);
        gh.x = rtf(g.x); gl.x = rtf(g.x - gh.x);
        gh.y = rtf(g.y); gl.y = rtf(g.y - gh.y);
        gh.z = rtf(g.z); gl.z = rtf(g.z - gh.z);
        gh.w = rtf(g.w); gl.w = rtf(g.w - gh.w);
        *(float4*)&sFh[off] = fh;
        *(float4*)&sFl[off] = fl;
        *(float4*)&sGh[off] = gh;
        *(float4*)&sGl[off] = gl;
    }
    __syncthreads();

    // GEMM1 (tf32x3): S[wr][v] = sum_h F[h][wr] * G[h][v]
    // warp covers rows [16mt,16mt+16) x cols [32nh, 32nh+32)
    float acc[4][4];
#pragma unroll
    for (int nj = 0; nj < 4; nj++)
#pragma unroll
        for (int r = 0; r < 4; r++) acc[nj][r] = 0.f;

#pragma unroll
    for (int k0 = 0; k0 < 64; k0 += 8) {
        const int h0 = k0 + qc;
        const int wr = mt * 16 + qr;
        uint32_t Ah[4], Al[4];
        Ah[0] = __float_as_uint(sFh[h0 * 72 + wr]);
        Ah[1] = __float_as_uint(sFh[h0 * 72 + wr + 8]);
        Ah[2] = __float_as_uint(sFh[(h0 + 4) * 72 + wr]);
        Ah[3] = __float_as_uint(sFh[(h0 + 4) * 72 + wr + 8]);
        Al[0] = __float_as_uint(sFl[h0 * 72 + wr]);
        Al[1] = __float_as_uint(sFl[h0 * 72 + wr + 8]);
        Al[2] = __float_as_uint(sFl[(h0 + 4) * 72 + wr]);
        Al[3] = __float_as_uint(sFl[(h0 + 4) * 72 + wr + 8]);
#pragma unroll
        for (int nj = 0; nj < 4; nj++) {
            const int v0 = nh * 32 + nj * 8 + qr;
            uint32_t Bh[2], Bl[2];
            Bh[0] = __float_as_uint(sGh[h0 * 72 + v0]);
            Bh[1] = __float_as_uint(sGh[(h0 + 4) * 72 + v0]);
            Bl[0] = __float_as_uint(sGl[h0 * 72 + v0]);
            Bl[1] = __float_as_uint(sGl[(h0 + 4) * 72 + v0]);
            mma_tf32(acc[nj], Ah, Bh);
            mma_tf32(acc[nj], Ah, Bl);
            mma_tf32(acc[nj], Al, Bh);
        }
    }

    // split softmax: per-warp partial (max, sum) over this 32-col half
    float mlo = -1e30f, mhi = -1e30f;
#pragma unroll
    for (int nj = 0; nj < 4; nj++) {
        mlo = fmaxf(mlo, fmaxf(acc[nj][0], acc[nj][1]));
        mhi = fmaxf(mhi, fmaxf(acc[nj][2], acc[nj][3]));
    }
    mlo = fmaxf(mlo, __shfl_xor_sync(0xffffffffu, mlo, 1));
    mlo = fmaxf(mlo, __shfl_xor_sync(0xffffffffu, mlo, 2));
    mhi = fmaxf(mhi, __shfl_xor_sync(0xffffffffu, mhi, 1));
    mhi = fmaxf(mhi, __shfl_xor_sync(0xffffffffu, mhi, 2));
    float slo = 0.f, shi = 0.f;
#pragma unroll
    for (int nj = 0; nj < 4; nj++) {
        acc[nj][0] = __expf(acc[nj][0] - mlo);
        acc[nj][1] = __expf(acc[nj][1] - mlo);
        acc[nj][2] = __expf(acc[nj][2] - mhi);
        acc[nj][3] = __expf(acc[nj][3] - mhi);
        slo += acc[nj][0] + acc[nj][1];
        shi += acc[nj][2] + acc[nj][3];
    }
    slo += __shfl_xor_sync(0xffffffffu, slo, 1);
    slo += __shfl_xor_sync(0xffffffffu, slo, 2);
    shi += __shfl_xor_sync(0xffffffffu, shi, 1);
    shi += __shfl_xor_sync(0xffffffffu, shi, 2);

    const int rlo = mt * 16 + qr, rhi = rlo + 8;
    if (qc == 0) {
        red[rlo * 4 + nh * 2]     = mlo;
        red[rlo * 4 + nh * 2 + 1] = slo;
        red[rhi * 4 + nh * 2]     = mhi;
        red[rhi * 4 + nh * 2 + 1] = shi;
    }
    __syncthreads();   // also: all GEMM1 reads of sF*/sG* complete

    // combine the two halves; rescale this warp's probabilities
    float scl_lo, scl_hi;
    {
        float4 r4 = *(const float4*)&red[rlo * 4];
        float M = fmaxf(r4.x, r4.z);
        float den = r4.y * __expf(r4.x - M) + r4.w * __expf(r4.z - M);
        scl_lo = __expf(mlo - M) / den;
        r4 = *(const float4*)&red[rhi * 4];
        M = fmaxf(r4.x, r4.z);
        den = r4.y * __expf(r4.x - M) + r4.w * __expf(r4.z - M);
        scl_hi = __expf(mhi - M) / den;
    }

    // stage tf32 attn into sAt[w][v] (stride 72), tf32 Hm into sHm[h][w] (stride 68)
    float* sHm = smp;          // overlays Fh
    float* sAt = smp + 4608;   // overlays Fl
    {
        const int wlo = mt * 16 + qr, whi = wlo + 8;
#pragma unroll
        for (int nj = 0; nj < 4; nj++) {
            const int v = nh * 32 + nj * 8 + 2 * qc;
            float2 lo = make_float2(rtf(acc[nj][0] * scl_lo), rtf(acc[nj][1] * scl_lo));
            float2 hi = make_float2(rtf(acc[nj][2] * scl_hi), rtf(acc[nj][3] * scl_hi));
            *(float2*)&sAt[wlo * 72 + v] = lo;
            *(float2*)&sAt[whi * 72 + v] = hi;
        }
    }
    for (int i = tid * 4; i < 4096; i += 1024) {
        float4 v = *(const float4*)&Hm[i];
        v.x = rtf(v.x); v.y = rtf(v.y); v.z = rtf(v.z); v.w = rtf(v.w);
        *(float4*)&sHm[(i >> 6) * 68 + (i & 63)] = v;
    }
    __syncthreads();

    // GEMM2 (tf32): C[v][h] = sum_w attn[w][v] * Hm[h][w]  (= O^T)
    // warp covers v rows [16mt,16mt+16) x h cols [32nh, 32nh+32)
#pragma unroll
    for (int nj = 0; nj < 4; nj++)
#pragma unroll
        for (int r = 0; r < 4; r++) acc[nj][r] = 0.f;

#pragma unroll
    for (int k0 = 0; k0 < 64; k0 += 8) {
        const int w0 = k0 + qc;
        const int vv = mt * 16 + qr;
        uint32_t af[4];
        af[0] = __float_as_uint(sAt[w0 * 72 + vv]);
        af[1] = __float_as_uint(sAt[w0 * 72 + vv + 8]);
        af[2] = __float_as_uint(sAt[(w0 + 4) * 72 + vv]);
        af[3] = __float_as_uint(sAt[(w0 + 4) * 72 + vv + 8]);
#pragma unroll
        for (int nj = 0; nj < 4; nj++) {
            const int hh = nh * 32 + nj * 8 + qr;
            uint32_t bfr[2];
            bfr[0] = __float_as_uint(sHm[hh * 68 + w0]);
            bfr[1] = __float_as_uint(sHm[hh * 68 + w0 + 4]);
            mma_tf32(acc[nj], af, bfr);
        }
    }

    // store O[h][v] (tf32-rounded for the final conv)
    float* O = o + (size_t)bc * HW;
    const int vr = mt * 16 + qr;
#pragma unroll
    for (int nj = 0; nj < 4; nj++) {
        const int hc = nh * 32 + nj * 8 + 2 * qc;
        O[hc * 64 + vr]           = rtf(acc[nj][0]);
        O[(hc + 1) * 64 + vr]     = rtf(acc[nj][1]);
        O[hc * 64 + vr + 8]       = rtf(acc[nj][2]);
        O[(hc + 1) * 64 + vr + 8] = rtf(acc[nj][3]);
    }
}

// ---------------------------------------------------------------------------
extern "C" void kernel_launch(void* const* d_in, const int* in_sizes, int n_in,
                              void* d_out, int out_size) {
    const float* x  = (const float*)d_in[0];
    const float* wf = (const float*)d_in[1];
    const float* bf = (const float*)d_in[2];
    const float* wg = (const float*)d_in[3];
    const float* bg = (const float*)d_in[4];
    const float* wh = (const float*)d_in[5];
    const float* bh = (const float*)d_in[6];
    const float* wv = (const float*)d_in[7];
    const float* bv = (const float*)d_in[8];

    float *yb, *ob, *xr, *wt, *wtv, *bcat;
    cudaGetSymbolAddress((void**)&yb,   g_y);
    cudaGetSymbolAddress((void**)&ob,   g_o);
    cudaGetSymbolAddress((void**)&xr,   g_xr);
    cudaGetSymbolAddress((void**)&wt,   g_wt);
    cudaGetSymbolAddress((void**)&wtv,  g_wtv);
    cudaGetSymbolAddress((void**)&bcat, g_bcat);

    cudaFuncSetAttribute(conv_hmma_kernel,
                         cudaFuncAttributeMaxDynamicSharedMemorySize, CONV_SMEM);
    cudaFuncSetAttribute(attn_kernel,
                         cudaFuncAttributeMaxDynamicSharedMemorySize, ATT_SMEM);

    // 1) weight transpose + rounding; x rounding
    prep_kernel<<<768, 256>>>(wf, wg, wh, wv, bf, bg, bh);
    round_x_kernel<<<16384, 256>>>(x);

    // 2) fused f/g/h conv: M=768 (6 tiles), N=4096 (32 tiles), B=16
    conv_hmma_kernel<<<dim3(32, 6, 16), 256, CONV_SMEM>>>(xr, wt, bcat, yb, 768);

    // 3) per-(b,c) attention
    attn_kernel<<<4096, 256, ATT_SMEM>>>(yb, ob);

    // 4) output conv: M=256 (2 tiles)
    conv_hmma_kernel<<<dim3(32, 2, 16), 256, CONV_SMEM>>>(ob, wtv, bv, (float*)d_out, 256);
}

// round 8
// speedup vs baseline: 1.1599x; 1.0387x over previous
#include <cuda_runtime.h>
#include <math.h>
#include <stdint.h>

#define BATCH 16
#define HW    4096
#define CHW   1048576u

// Scratch (no allocation allowed -> __device__ globals)
__device__ float g_y[3ull * 16777216ull];   // fx, gx, hx
__device__ float g_o[16777216ull];          // attention output (tf32-rounded)
__device__ float g_xrF[16777216ull];        // x, tf32-rounded, B-fragment layout
__device__ float g_wtF[768 * 256];          // concat(wf,wg,wh), A-fragment layout
__device__ float g_wtvF[256 * 256];         // wv, A-fragment layout
__device__ float g_bcat[768];

__device__ __forceinline__ uint32_t f2tf32(float v) {   // round-to-nearest (unbiased)
    uint32_t r;
    asm("cvt.rna.tf32.f32 %0, %1;" : "=r"(r) : "f"(v));
    return r;
}
__device__ __forceinline__ float rtf(float v) { return __uint_as_float(f2tf32(v)); }

__device__ __forceinline__ void mma_tf32(float* c, const uint32_t* a, const uint32_t* b) {
    asm volatile(
        "mma.sync.aligned.m16n8k8.row.col.f32.tf32.tf32.f32 "
        "{%0,%1,%2,%3}, {%4,%5,%6,%7}, {%8,%9}, {%0,%1,%2,%3};"
        : "+f"(c[0]), "+f"(c[1]), "+f"(c[2]), "+f"(c[3])
        : "r"(a[0]), "r"(a[1]), "r"(a[2]), "r"(a[3]), "r"(b[0]), "r"(b[1]));
}

__device__ __forceinline__ void cpa16(uint32_t s, const void* g) {
    asm volatile("cp.async.cg.shared.global [%0], [%1], 16;" :: "r"(s), "l"(g));
}
#define CP_COMMIT()  asm volatile("cp.async.commit_group;" ::: "memory")
#define CP_WAIT2()   asm volatile("cp.async.wait_group 2;" ::: "memory")

// ---------------------------------------------------------------------------
// Prep: weights -> A-fragment layout, tf32-rounded; concat biases.
// A-frag layout per 128-row m-tile: float4 index = ((mt*16+ks)*2+kk)*8+mf)*32+lane
//   mf = mw*4+mi ; qr=lane>>2, qc=lane&3 ; m = mt*128+mw*64+mi*16+qr
//   k = ks*16+kk*8+qc ; float4 = {W[m][k], W[m+8][k], W[m][k+4], W[m+8][k+4]}
// ---------------------------------------------------------------------------
__global__ void prep_w_kernel(const float* __restrict__ wf, const float* __restrict__ wg,
                              const float* __restrict__ wh, const float* __restrict__ wv,
                              const float* __restrict__ bf, const float* __restrict__ bg,
                              const float* __restrict__ bh) {
    int idx = blockIdx.x * 256 + threadIdx.x;   // < 65536 float4s total
    int lane = idx & 31;
    int t1 = idx >> 5;
    int mf = t1 & 7;  t1 >>= 3;
    int kk = t1 & 1;  t1 >>= 1;
    int ks = t1 & 15; t1 >>= 4;    // t1 now = mt (0..5 conv1, then 0..1 conv2)
    int qr = lane >> 2, qc = lane & 3;
    int k = ks * 16 + kk * 8 + qc;
    float4 v;
    if (idx < 49152) {             // conv1 weights: mt 0..5
        int m = t1 * 128 + (mf >> 2) * 64 + (mf & 3) * 16 + qr;
        const float* w = (m < 256) ? wf : (m < 512) ? wg : wh;
        int mm = m & 255;
        v.x = rtf(w[mm * 256 + k]);
        v.y = rtf(w[(mm + 8) * 256 + k]);
        v.z = rtf(w[mm * 256 + k + 4]);
        v.w = rtf(w[(mm + 8) * 256 + k + 4]);
        *(float4*)&g_wtF[idx * 4] = v;
    } else {                       // conv2 weights: idx2 < 16384, mt 0..1
        int idx2 = idx - 49152;
        int t2 = idx2 >> 5;
        int mf2 = t2 & 7;  t2 >>= 3;
        int kk2 = t2 & 1;  t2 >>= 1;
        int ks2 = t2 & 15; t2 >>= 4;
        int k2 = ks2 * 16 + kk2 * 8 + (idx2 & 3 & 3);   // qc from same lane
        int lane2 = idx2 & 31;
        int qr2 = lane2 >> 2, qc2 = lane2 & 3;
        k2 = ks2 * 16 + kk2 * 8 + qc2;
        int m = t2 * 128 + (mf2 >> 2) * 64 + (mf2 & 3) * 16 + qr2;
        v.x = rtf(wv[m * 256 + k2]);
        v.y = rtf(wv[(m + 8) * 256 + k2]);
        v.z = rtf(wv[m * 256 + k2 + 4]);
        v.w = rtf(wv[(m + 8) * 256 + k2 + 4]);
        *(float4*)&g_wtvF[idx2 * 4] = v;
    }
    if (idx < 256) {
        g_bcat[idx]       = bf[idx];
        g_bcat[256 + idx] = bg[idx];
        g_bcat[512 + idx] = bh[idx];
    }
}

// ---------------------------------------------------------------------------
// x -> B-fragment layout, tf32-rounded. float2 index:
//   ((((((b*32+nt)*16+ks)*2+kk)*16+nf)*32+lane) ; nf = nw*4+nj
//   n = nt*128+nw*32+nj*8+qr ; k = ks*16+kk*8+qc ; float2 = {x[k][n], x[k+4][n]}
// ---------------------------------------------------------------------------
__global__ void x_frag_kernel(const float* __restrict__ x) {
    int idx = blockIdx.x * 256 + threadIdx.x;   // 8388608 float2s
    int lane = idx & 31;
    int t1 = idx >> 5;
    int nf = t1 & 15; t1 >>= 4;
    int kk = t1 & 1;  t1 >>= 1;
    int ks = t1 & 15; t1 >>= 4;
    int nt = t1 & 31; t1 >>= 5;    // t1 now = b
    int n = nt * 128 + (nf >> 2) * 32 + (nf & 3) * 8 + (lane >> 2);
    int k = ks * 16 + kk * 8 + (lane & 3);
    const float* xb = x + (size_t)t1 * CHW;
    float2 v;
    v.x = rtf(xb[(size_t)k * HW + n]);
    v.y = rtf(xb[(size_t)(k + 4) * HW + n]);
    *(float2*)&g_xrF[(size_t)idx * 2] = v;
}

// ---------------------------------------------------------------------------
// HMMA tf32 conv GEMM. A always fragment layout. B: fragment layout (BFRAG,
// conv1) or row layout with SSTRIDE padding (conv2, input g_o).
// CTA 128x128, k-tile 16, 4-stage cp.async, 8 warps (2m x 4n), warp 64x32.
// ---------------------------------------------------------------------------
#define SSTRIDE 136
#define SA(s)       ((s) * 2048)
#define SBF(s)      (8192 + (s) * 2048)
#define SBR(s, kr)  (8192 + (s) * 2176 + (kr) * SSTRIDE)
#define CONV_SMEM   ((8192 + 4 * 2176) * 4)   // 67584 B

template <bool BFRAG>
__global__ __launch_bounds__(256, 2)
void conv_mma_kernel(const float* __restrict__ XB, const float* __restrict__ WTF,
                     const float* __restrict__ bias, float* __restrict__ Y) {
    extern __shared__ uint32_t dsm[];

    const int tid  = threadIdx.x;
    const int lane = tid & 31;
    const int warp = tid >> 5;
    const int mw   = warp >> 2;
    const int nw   = warp & 3;
    const int b    = blockIdx.z;
    const int nt   = blockIdx.x;
    const int n0   = nt * 128;
    const int mt   = blockIdx.y;
    const int m0   = mt * 128;

    const uint32_t sbase = (uint32_t)__cvta_generic_to_shared(dsm);
    const float* gA = WTF + (size_t)(mt * 16) * 2048;                 // +s*2048
    const float* gBF = XB + ((size_t)(b * 32 + nt) * 16) * 2048;      // BFRAG source
    const float* gBR = XB + (size_t)b * CHW + n0;                     // row source

    float acc[4][4][4];
#pragma unroll
    for (int i = 0; i < 4; i++)
#pragma unroll
        for (int j = 0; j < 4; j++)
#pragma unroll
            for (int r = 0; r < 4; r++) acc[i][j][r] = 0.f;

    // --- loaders (2 x 16B per operand per stage per thread) ---
    auto load_stage = [&](int s, int buf) {
#pragma unroll
        for (int h = 0; h < 2; h++) {
            int c = tid + h * 256;   // 0..511
            cpa16(sbase + (SA(buf) + c * 4) * 4, gA + (size_t)s * 2048 + c * 4);
            if (BFRAG) {
                cpa16(sbase + (SBF(buf) + c * 4) * 4, gBF + (size_t)s * 2048 + c * 4);
            } else {
                int kr = c >> 5, nc = (c & 31) * 4;
                cpa16(sbase + (SBR(buf, kr) + nc) * 4,
                      gBR + (size_t)(s * 16 + kr) * HW + nc);
            }
        }
    };

#pragma unroll
    for (int s = 0; s < 3; s++) { load_stage(s, s); CP_COMMIT(); }

    for (int kt = 0; kt < 16; kt++) {
        const int buf = kt & 3;
        CP_WAIT2();
        __syncthreads();

        if (kt < 13) load_stage(kt + 3, (kt + 3) & 3);
        CP_COMMIT();

#pragma unroll
        for (int kk = 0; kk < 2; kk++) {
            uint32_t af[4][4];
#pragma unroll
            for (int mi = 0; mi < 4; mi++) {
                const uint4 a4 = *(const uint4*)
                    &dsm[SA(buf) + ((kk * 8 + mw * 4 + mi) * 32 + lane) * 4];
                af[mi][0] = a4.x; af[mi][1] = a4.y; af[mi][2] = a4.z; af[mi][3] = a4.w;
            }
            uint32_t bfr[4][2];
            if (BFRAG) {
#pragma unroll
                for (int nj = 0; nj < 4; nj++) {
                    const uint2 b2 = *(const uint2*)
                        &dsm[SBF(buf) + ((kk * 16 + nw * 4 + nj) * 32 + lane) * 2];
                    bfr[nj][0] = b2.x; bfr[nj][1] = b2.y;
                }
            } else {
                const int qc = lane & 3, qr = lane >> 2;
                const uint32_t* B0 = dsm + SBR(buf, kk * 8 + qc) + nw * 32 + qr;
#pragma unroll
                for (int nj = 0; nj < 4; nj++) {
                    bfr[nj][0] = B0[nj * 8];
                    bfr[nj][1] = B0[4 * SSTRIDE + nj * 8];
                }
            }
#pragma unroll
            for (int mi = 0; mi < 4; mi++)
#pragma unroll
                for (int nj = 0; nj < 4; nj++)
                    mma_tf32(acc[mi][nj], af[mi], bfr[nj]);
        }
        __syncthreads();
    }

    // epilogue: bias + v2 stores in accumulator layout (handles concat scatter)
#pragma unroll
    for (int mi = 0; mi < 4; mi++) {
        int mr0 = m0 + mw * 64 + mi * 16 + (lane >> 2);
        float bv0 = bias[mr0];
        float bv1 = bias[mr0 + 8];
        float* y0 = Y + ((size_t)(mr0 >> 8) * BATCH + b) * CHW + (size_t)(mr0 & 255) * HW + n0;
        int mr1 = mr0 + 8;
        float* y1 = Y + ((size_t)(mr1 >> 8) * BATCH + b) * CHW + (size_t)(mr1 & 255) * HW + n0;
#pragma unroll
        for (int nj = 0; nj < 4; nj++) {
            int nc = nw * 32 + nj * 8 + 2 * (lane & 3);
            float2 v0 = make_float2(acc[mi][nj][0] + bv0, acc[mi][nj][1] + bv0);
            float2 v1 = make_float2(acc[mi][nj][2] + bv1, acc[mi][nj][3] + bv1);
            *(float2*)(y0 + nc) = v0;
            *(float2*)(y1 + nc) = v1;
        }
    }
}

// ---------------------------------------------------------------------------
// Fused attention (unchanged from round 7): 256 threads, tf32x3 GEMM1,
// split softmax, tf32 GEMM2.
// ---------------------------------------------------------------------------
#define ATT_SMEM 74752

__global__ __launch_bounds__(256)
void attn_kernel(const float* __restrict__ y, float* __restrict__ o) {
    extern __shared__ float smp[];
    const int bc = blockIdx.x;
    const size_t BCHW = (size_t)BATCH * CHW;
    const float* F  = y + (size_t)bc * HW;
    const float* G  = y + BCHW + (size_t)bc * HW;
    const float* Hm = y + 2 * BCHW + (size_t)bc * HW;

    float* sFh = smp;
    float* sFl = smp + 4608;
    float* sGh = smp + 9216;
    float* sGl = smp + 13824;
    float* red = smp + 18432;

    const int tid  = threadIdx.x;
    const int lane = tid & 31;
    const int warp = tid >> 5;
    const int mt   = warp >> 1;
    const int nh   = warp & 1;
    const int qr   = lane >> 2;
    const int qc   = lane & 3;

    for (int i = tid * 4; i < 4096; i += 1024) {
        float4 f = *(const float4*)&F[i];
        float4 g = *(const float4*)&G[i];
        int off = (i >> 6) * 72 + (i & 63);
        float4 fh, fl, gh, gl;
        fh.x = rtf(f.x); fl.x = rtf(f.x - fh.x);
        fh.y = rtf(f.y); fl.y = rtf(f.y - fh.y);
        fh.z = rtf(f.z); fl.z = rtf(f.z - fh.z);
        fh.w = rtf(f.w); fl.w = rtf(f.w - fh.w);
        gh.x = rtf(g.x); gl.x = rtf(g.x - gh.x);
        gh.y = rtf(g.y); gl.y = rtf(g.y - gh.y);
        gh.z = rtf(g.z); gl.z = rtf(g.z - gh.z);
        gh.w = rtf(g.w); gl.w = rtf(g.w - gh.w);
        *(float4*)&sFh[off] = fh;
        *(float4*)&sFl[off] = fl;
        *(float4*)&sGh[off] = gh;
        *(float4*)&sGl[off] = gl;
    }
    __syncthreads();

    float acc[4][4];
#pragma unroll
    for (int nj = 0; nj < 4; nj++)
#pragma unroll
        for (int r = 0; r < 4; r++) acc[nj][r] = 0.f;

#pragma unroll
    for (int k0 = 0; k0 < 64; k0 += 8) {
        const int h0 = k0 + qc;
        const int wr = mt * 16 + qr;
        uint32_t Ah[4], Al[4];
        Ah[0] = __float_as_uint(sFh[h0 * 72 + wr]);
        Ah[1] = __float_as_uint(sFh[h0 * 72 + wr + 8]);
        Ah[2] = __float_as_uint(sFh[(h0 + 4) * 72 + wr]);
        Ah[3] = __float_as_uint(sFh[(h0 + 4) * 72 + wr + 8]);
        Al[0] = __float_as_uint(sFl[h0 * 72 + wr]);
        Al[1] = __float_as_uint(sFl[h0 * 72 + wr + 8]);
        Al[2] = __float_as_uint(sFl[(h0 + 4) * 72 + wr]);
        Al[3] = __float_as_uint(sFl[(h0 + 4) * 72 + wr + 8]);
#pragma unroll
        for (int nj = 0; nj < 4; nj++) {
            const int v0 = nh * 32 + nj * 8 + qr;
            uint32_t Bh[2], Bl[2];
            Bh[0] = __float_as_uint(sGh[h0 * 72 + v0]);
            Bh[1] = __float_as_uint(sGh[(h0 + 4) * 72 + v0]);
            Bl[0] = __float_as_uint(sGl[h0 * 72 + v0]);
            Bl[1] = __float_as_uint(sGl[(h0 + 4) * 72 + v0]);
            mma_tf32(acc[nj], Ah, Bh);
            mma_tf32(acc[nj], Ah, Bl);
            mma_tf32(acc[nj], Al, Bh);
        }
    }

    float mlo = -1e30f, mhi = -1e30f;
#pragma unroll
    for (int nj = 0; nj < 4; nj++) {
        mlo = fmaxf(mlo, fmaxf(acc[nj][0], acc[nj][1]));
        mhi = fmaxf(mhi, fmaxf(acc[nj][2], acc[nj][3]));
    }
    mlo = fmaxf(mlo, __shfl_xor_sync(0xffffffffu, mlo, 1));
    mlo = fmaxf(mlo, __shfl_xor_sync(0xffffffffu, mlo, 2));
    mhi = fmaxf(mhi, __shfl_xor_sync(0xffffffffu, mhi, 1));
    mhi = fmaxf(mhi, __shfl_xor_sync(0xffffffffu, mhi, 2));
    float slo = 0.f, shi = 0.f;
#pragma unroll
    for (int nj = 0; nj < 4; nj++) {
        acc[nj][0] = __expf(acc[nj][0] - mlo);
        acc[nj][1] = __expf(acc[nj][1] - mlo);
        acc[nj][2] = __expf(acc[nj][2] - mhi);
        acc[nj][3] = __expf(acc[nj][3] - mhi);
        slo += acc[nj][0] + acc[nj][1];
        shi += acc[nj][2] + acc[nj][3];
    }
    slo += __shfl_xor_sync(0xffffffffu, slo, 1);
    slo += __shfl_xor_sync(0xffffffffu, slo, 2);
    shi += __shfl_xor_sync(0xffffffffu, shi, 1);
    shi += __shfl_xor_sync(0xffffffffu, shi, 2);

    const int rlo = mt * 16 + qr, rhi = rlo + 8;
    if (qc == 0) {
        red[rlo * 4 + nh * 2]     = mlo;
        red[rlo * 4 + nh * 2 + 1] = slo;
        red[rhi * 4 + nh * 2]     = mhi;
        red[rhi * 4 + nh * 2 + 1] = shi;
    }
    __syncthreads();

    float scl_lo, scl_hi;
    {
        float4 r4 = *(const float4*)&red[rlo * 4];
        float M = fmaxf(r4.x, r4.z);
        float den = r4.y * __expf(r4.x - M) + r4.w * __expf(r4.z - M);
        scl_lo = __expf(mlo - M) / den;
        r4 = *(const float4*)&red[rhi * 4];
        M = fmaxf(r4.x, r4.z);
        den = r4.y * __expf(r4.x - M) + r4.w * __expf(r4.z - M);
        scl_hi = __expf(mhi - M) / den;
    }

    float* sHm = smp;
    float* sAt = smp + 4608;
    {
        const int wlo = mt * 16 + qr, whi = wlo + 8;
#pragma unroll
        for (int nj = 0; nj < 4; nj++) {
            const int v = nh * 32 + nj * 8 + 2 * qc;
            float2 lo = make_float2(rtf(acc[nj][0] * scl_lo), rtf(acc[nj][1] * scl_lo));
            float2 hi = make_float2(rtf(acc[nj][2] * scl_hi), rtf(acc[nj][3] * scl_hi));
            *(float2*)&sAt[wlo * 72 + v] = lo;
            *(float2*)&sAt[whi * 72 + v] = hi;
        }
    }
    for (int i = tid * 4; i < 4096; i += 1024) {
        float4 v = *(const float4*)&Hm[i];
        v.x = rtf(v.x); v.y = rtf(v.y); v.z = rtf(v.z); v.w = rtf(v.w);
        *(float4*)&sHm[(i >> 6) * 68 + (i & 63)] = v;
    }
    __syncthreads();

#pragma unroll
    for (int nj = 0; nj < 4; nj++)
#pragma unroll
        for (int r = 0; r < 4; r++) acc[nj][r] = 0.f;

#pragma unroll
    for (int k0 = 0; k0 < 64; k0 += 8) {
        const int w0 = k0 + qc;
        const int vv = mt * 16 + qr;
        uint32_t af[4];
        af[0] = __float_as_uint(sAt[w0 * 72 + vv]);
        af[1] = __float_as_uint(sAt[w0 * 72 + vv + 8]);
        af[2] = __float_as_uint(sAt[(w0 + 4) * 72 + vv]);
        af[3] = __float_as_uint(sAt[(w0 + 4) * 72 + vv + 8]);
#pragma unroll
        for (int nj = 0; nj < 4; nj++) {
            const int hh = nh * 32 + nj * 8 + qr;
            uint32_t bfr[2];
            bfr[0] = __float_as_uint(sHm[hh * 68 + w0]);
            bfr[1] = __float_as_uint(sHm[hh * 68 + w0 + 4]);
            mma_tf32(acc[nj], af, bfr);
        }
    }

    float* O = o + (size_t)bc * HW;
    const int vr = mt * 16 + qr;
#pragma unroll
    for (int nj = 0; nj < 4; nj++) {
        const int hc = nh * 32 + nj * 8 + 2 * qc;
        O[hc * 64 + vr]           = rtf(acc[nj][0]);
        O[(hc + 1) * 64 + vr]     = rtf(acc[nj][1]);
        O[hc * 64 + vr + 8]       = rtf(acc[nj][2]);
        O[(hc + 1) * 64 + vr + 8] = rtf(acc[nj][3]);
    }
}

// ---------------------------------------------------------------------------
extern "C" void kernel_launch(void* const* d_in, const int* in_sizes, int n_in,
                              void* d_out, int out_size) {
    const float* x  = (const float*)d_in[0];
    const float* wf = (const float*)d_in[1];
    const float* bf = (const float*)d_in[2];
    const float* wg = (const float*)d_in[3];
    const float* bg = (const float*)d_in[4];
    const float* wh = (const float*)d_in[5];
    const float* bh = (const float*)d_in[6];
    const float* wv = (const float*)d_in[7];
    const float* bv = (const float*)d_in[8];

    float *yb, *ob, *xrF, *wtF, *wtvF, *bcat;
    cudaGetSymbolAddress((void**)&yb,   g_y);
    cudaGetSymbolAddress((void**)&ob,   g_o);
    cudaGetSymbolAddress((void**)&xrF,  g_xrF);
    cudaGetSymbolAddress((void**)&wtF,  g_wtF);
    cudaGetSymbolAddress((void**)&wtvF, g_wtvF);
    cudaGetSymbolAddress((void**)&bcat, g_bcat);

    cudaFuncSetAttribute(conv_mma_kernel<true>,
                         cudaFuncAttributeMaxDynamicSharedMemorySize, CONV_SMEM);
    cudaFuncSetAttribute(conv_mma_kernel<false>,
                         cudaFuncAttributeMaxDynamicSharedMemorySize, CONV_SMEM);
    cudaFuncSetAttribute(attn_kernel,
                         cudaFuncAttributeMaxDynamicSharedMemorySize, ATT_SMEM);

    // 1) weights -> fragment layout; x -> fragment layout (tf32-rounded)
    prep_w_kernel<<<256, 256>>>(wf, wg, wh, wv, bf, bg, bh);
    x_frag_kernel<<<32768, 256>>>(x);

    // 2) fused f/g/h conv: M=768 (6 tiles), N=4096 (32 tiles), B=16
    conv_mma_kernel<true><<<dim3(32, 6, 16), 256, CONV_SMEM>>>(xrF, wtF, bcat, yb);

    // 3) per-(b,c) attention
    attn_kernel<<<4096, 256, ATT_SMEM>>>(yb, ob);

    // 4) output conv: M=256 (2 tiles), B from g_o in row layout
    conv_mma_kernel<false><<<dim3(32, 2, 16), 256, CONV_SMEM>>>(ob, wtvF, bv, (float*)d_out);
}

// round 9
// speedup vs baseline: 1.2234x; 1.0548x over previous
#include <cuda_runtime.h>
#include <cuda_bf16.h>
#include <math.h>
#include <stdint.h>

#define BATCH 16
#define HW    4096
#define CHW   1048576u

// Scratch (no allocation allowed -> __device__ globals)
__device__ float g_y[3ull * 16777216ull];   // fx, gx, hx
__device__ float g_o[16777216ull];          // attention output (tf32-rounded)
__device__ float g_xrF[16777216ull];        // x, tf32-rounded, B-fragment layout
__device__ float g_wtF[768 * 256];          // concat(wf,wg,wh), A-fragment layout
__device__ float g_wtvF[256 * 256];         // wv, A-fragment layout
__device__ float g_bcat[768];

__device__ __forceinline__ uint32_t f2tf32(float v) {
    uint32_t r;
    asm("cvt.rna.tf32.f32 %0, %1;" : "=r"(r) : "f"(v));
    return r;
}
__device__ __forceinline__ float rtf(float v) { return __uint_as_float(f2tf32(v)); }

__device__ __forceinline__ void mma_tf32(float* c, const uint32_t* a, const uint32_t* b) {
    asm volatile(
        "mma.sync.aligned.m16n8k8.row.col.f32.tf32.tf32.f32 "
        "{%0,%1,%2,%3}, {%4,%5,%6,%7}, {%8,%9}, {%0,%1,%2,%3};"
        : "+f"(c[0]), "+f"(c[1]), "+f"(c[2]), "+f"(c[3])
        : "r"(a[0]), "r"(a[1]), "r"(a[2]), "r"(a[3]), "r"(b[0]), "r"(b[1]));
}

__device__ __forceinline__ void mma_bf16(float* c, const uint32_t* a, const uint32_t* b) {
    asm volatile(
        "mma.sync.aligned.m16n8k16.row.col.f32.bf16.bf16.f32 "
        "{%0,%1,%2,%3}, {%4,%5,%6,%7}, {%8,%9}, {%0,%1,%2,%3};"
        : "+f"(c[0]), "+f"(c[1]), "+f"(c[2]), "+f"(c[3])
        : "r"(a[0]), "r"(a[1]), "r"(a[2]), "r"(a[3]), "r"(b[0]), "r"(b[1]));
}

// pack two f32 into bf16x2: low half = lo_elem (even index), high = hi_elem (odd)
__device__ __forceinline__ uint32_t bfpack(float lo_elem, float hi_elem) {
    uint32_t r;
    asm("cvt.rn.bf16x2.f32 %0, %2, %1;" : "=r"(r) : "f"(lo_elem), "f"(hi_elem));
    return r;
}
// hi/lo bf16x2 split of an element pair
__device__ __forceinline__ void bfsplit2(float x0, float x1, uint32_t& hi, uint32_t& lo) {
    hi = bfpack(x0, x1);
    float h0 = __uint_as_float(hi << 16);
    float h1 = __uint_as_float(hi & 0xffff0000u);
    lo = bfpack(x0 - h0, x1 - h1);
}

__device__ __forceinline__ void cpa16(uint32_t s, const void* g) {
    asm volatile("cp.async.cg.shared.global [%0], [%1], 16;" :: "r"(s), "l"(g));
}
#define CP_COMMIT()  asm volatile("cp.async.commit_group;" ::: "memory")
#define CP_WAIT2()   asm volatile("cp.async.wait_group 2;" ::: "memory")

// ---------------------------------------------------------------------------
// Prep: weights -> A-fragment layout, tf32-rounded; concat biases. (unchanged)
// ---------------------------------------------------------------------------
__global__ void prep_w_kernel(const float* __restrict__ wf, const float* __restrict__ wg,
                              const float* __restrict__ wh, const float* __restrict__ wv,
                              const float* __restrict__ bf, const float* __restrict__ bg,
                              const float* __restrict__ bh) {
    int idx = blockIdx.x * 256 + threadIdx.x;
    int lane = idx & 31;
    int t1 = idx >> 5;
    int mf = t1 & 7;  t1 >>= 3;
    int kk = t1 & 1;  t1 >>= 1;
    int ks = t1 & 15; t1 >>= 4;
    int qr = lane >> 2, qc = lane & 3;
    int k = ks * 16 + kk * 8 + qc;
    float4 v;
    if (idx < 49152) {
        int m = t1 * 128 + (mf >> 2) * 64 + (mf & 3) * 16 + qr;
        const float* w = (m < 256) ? wf : (m < 512) ? wg : wh;
        int mm = m & 255;
        v.x = rtf(w[mm * 256 + k]);
        v.y = rtf(w[(mm + 8) * 256 + k]);
        v.z = rtf(w[mm * 256 + k + 4]);
        v.w = rtf(w[(mm + 8) * 256 + k + 4]);
        *(float4*)&g_wtF[idx * 4] = v;
    } else {
        int idx2 = idx - 49152;
        int t2 = idx2 >> 5;
        int mf2 = t2 & 7;  t2 >>= 3;
        int kk2 = t2 & 1;  t2 >>= 1;
        int ks2 = t2 & 15; t2 >>= 4;
        int lane2 = idx2 & 31;
        int qr2 = lane2 >> 2, qc2 = lane2 & 3;
        int k2 = ks2 * 16 + kk2 * 8 + qc2;
        int m = t2 * 128 + (mf2 >> 2) * 64 + (mf2 & 3) * 16 + qr2;
        v.x = rtf(wv[m * 256 + k2]);
        v.y = rtf(wv[(m + 8) * 256 + k2]);
        v.z = rtf(wv[m * 256 + k2 + 4]);
        v.w = rtf(wv[(m + 8) * 256 + k2 + 4]);
        *(float4*)&g_wtvF[idx2 * 4] = v;
    }
    if (idx < 256) {
        g_bcat[idx]       = bf[idx];
        g_bcat[256 + idx] = bg[idx];
        g_bcat[512 + idx] = bh[idx];
    }
}

// x -> B-fragment layout, tf32-rounded (unchanged)
__global__ void x_frag_kernel(const float* __restrict__ x) {
    int idx = blockIdx.x * 256 + threadIdx.x;
    int lane = idx & 31;
    int t1 = idx >> 5;
    int nf = t1 & 15; t1 >>= 4;
    int kk = t1 & 1;  t1 >>= 1;
    int ks = t1 & 15; t1 >>= 4;
    int nt = t1 & 31; t1 >>= 5;
    int n = nt * 128 + (nf >> 2) * 32 + (nf & 3) * 8 + (lane >> 2);
    int k = ks * 16 + kk * 8 + (lane & 3);
    const float* xb = x + (size_t)t1 * CHW;
    float2 v;
    v.x = rtf(xb[(size_t)k * HW + n]);
    v.y = rtf(xb[(size_t)(k + 4) * HW + n]);
    *(float2*)&g_xrF[(size_t)idx * 2] = v;
}

// ---------------------------------------------------------------------------
// HMMA tf32 conv GEMM (unchanged from round 8)
// ---------------------------------------------------------------------------
#define SSTRIDE 136
#define SA(s)       ((s) * 2048)
#define SBF(s)      (8192 + (s) * 2048)
#define SBR(s, kr)  (8192 + (s) * 2176 + (kr) * SSTRIDE)
#define CONV_SMEM   ((8192 + 4 * 2176) * 4)

template <bool BFRAG>
__global__ __launch_bounds__(256, 2)
void conv_mma_kernel(const float* __restrict__ XB, const float* __restrict__ WTF,
                     const float* __restrict__ bias, float* __restrict__ Y) {
    extern __shared__ uint32_t dsm[];

    const int tid  = threadIdx.x;
    const int lane = tid & 31;
    const int warp = tid >> 5;
    const int mw   = warp >> 2;
    const int nw   = warp & 3;
    const int b    = blockIdx.z;
    const int nt   = blockIdx.x;
    const int n0   = nt * 128;
    const int mt   = blockIdx.y;
    const int m0   = mt * 128;

    const uint32_t sbase = (uint32_t)__cvta_generic_to_shared(dsm);
    const float* gA = WTF + (size_t)(mt * 16) * 2048;
    const float* gBF = XB + ((size_t)(b * 32 + nt) * 16) * 2048;
    const float* gBR = XB + (size_t)b * CHW + n0;

    float acc[4][4][4];
#pragma unroll
    for (int i = 0; i < 4; i++)
#pragma unroll
        for (int j = 0; j < 4; j++)
#pragma unroll
            for (int r = 0; r < 4; r++) acc[i][j][r] = 0.f;

    auto load_stage = [&](int s, int buf) {
#pragma unroll
        for (int h = 0; h < 2; h++) {
            int c = tid + h * 256;
            cpa16(sbase + (SA(buf) + c * 4) * 4, gA + (size_t)s * 2048 + c * 4);
            if (BFRAG) {
                cpa16(sbase + (SBF(buf) + c * 4) * 4, gBF + (size_t)s * 2048 + c * 4);
            } else {
                int kr = c >> 5, nc = (c & 31) * 4;
                cpa16(sbase + (SBR(buf, kr) + nc) * 4,
                      gBR + (size_t)(s * 16 + kr) * HW + nc);
            }
        }
    };

#pragma unroll
    for (int s = 0; s < 3; s++) { load_stage(s, s); CP_COMMIT(); }

    for (int kt = 0; kt < 16; kt++) {
        const int buf = kt & 3;
        CP_WAIT2();
        __syncthreads();

        if (kt < 13) load_stage(kt + 3, (kt + 3) & 3);
        CP_COMMIT();

#pragma unroll
        for (int kk = 0; kk < 2; kk++) {
            uint32_t af[4][4];
#pragma unroll
            for (int mi = 0; mi < 4; mi++) {
                const uint4 a4 = *(const uint4*)
                    &dsm[SA(buf) + ((kk * 8 + mw * 4 + mi) * 32 + lane) * 4];
                af[mi][0] = a4.x; af[mi][1] = a4.y; af[mi][2] = a4.z; af[mi][3] = a4.w;
            }
            uint32_t bfr[4][2];
            if (BFRAG) {
#pragma unroll
                for (int nj = 0; nj < 4; nj++) {
                    const uint2 b2 = *(const uint2*)
                        &dsm[SBF(buf) + ((kk * 16 + nw * 4 + nj) * 32 + lane) * 2];
                    bfr[nj][0] = b2.x; bfr[nj][1] = b2.y;
                }
            } else {
                const int qc = lane & 3, qr = lane >> 2;
                const uint32_t* B0 = dsm + SBR(buf, kk * 8 + qc) + nw * 32 + qr;
#pragma unroll
                for (int nj = 0; nj < 4; nj++) {
                    bfr[nj][0] = B0[nj * 8];
                    bfr[nj][1] = B0[4 * SSTRIDE + nj * 8];
                }
            }
#pragma unroll
            for (int mi = 0; mi < 4; mi++)
#pragma unroll
                for (int nj = 0; nj < 4; nj++)
                    mma_tf32(acc[mi][nj], af[mi], bfr[nj]);
        }
        __syncthreads();
    }

#pragma unroll
    for (int mi = 0; mi < 4; mi++) {
        int mr0 = m0 + mw * 64 + mi * 16 + (lane >> 2);
        float bv0 = bias[mr0];
        float bv1 = bias[mr0 + 8];
        float* y0 = Y + ((size_t)(mr0 >> 8) * BATCH + b) * CHW + (size_t)(mr0 & 255) * HW + n0;
        int mr1 = mr0 + 8;
        float* y1 = Y + ((size_t)(mr1 >> 8) * BATCH + b) * CHW + (size_t)(mr1 & 255) * HW + n0;
#pragma unroll
        for (int nj = 0; nj < 4; nj++) {
            int nc = nw * 32 + nj * 8 + 2 * (lane & 3);
            float2 v0 = make_float2(acc[mi][nj][0] + bv0, acc[mi][nj][1] + bv0);
            float2 v1 = make_float2(acc[mi][nj][2] + bv1, acc[mi][nj][3] + bv1);
            *(float2*)(y0 + nc) = v0;
            *(float2*)(y1 + nc) = v1;
        }
    }
}

// ---------------------------------------------------------------------------
// Fused attention, bf16x2 split on m16n8k16 MMAs, 256 threads, 8 warps.
//   warp w -> m-tile (w>>1) [16 rows], n-half (w&1) [32 cols]
// smem planes (u32, stride 35 words = 70 bf16 per row, 64 rows = 2240 words):
//   phase1: FtH@0 FtL@2240 GtH@4480 GtL@6720  ([w][h-pair] / [v][h-pair])
//   phase2: HmH@0 HmL@2240 AtH@4480 AtL@6720  ([h][w-pair] / [v][w-bf16])
//   red (f32) @8960 words.  Total 36864 B -> ~6 CTAs/SM.
// ---------------------------------------------------------------------------
#define PLW  35
#define PLSZ 2240
#define ATT_SMEM 36864

__global__ __launch_bounds__(256)
void attn_kernel(const float* __restrict__ y, float* __restrict__ o) {
    extern __shared__ uint32_t sm[];
    const int bc = blockIdx.x;
    const size_t BCHW = (size_t)BATCH * CHW;
    const float* F  = y + (size_t)bc * HW;
    const float* G  = y + BCHW + (size_t)bc * HW;
    const float* Hm = y + 2 * BCHW + (size_t)bc * HW;

    uint32_t* sFtH = sm;
    uint32_t* sFtL = sm + PLSZ;
    uint32_t* sGtH = sm + 2 * PLSZ;
    uint32_t* sGtL = sm + 3 * PLSZ;
    float*    red  = (float*)(sm + 4 * PLSZ);   // [64][4]

    const int tid  = threadIdx.x;
    const int lane = tid & 31;
    const int warp = tid >> 5;
    const int mt   = warp >> 1;
    const int nh   = warp & 1;
    const int qr   = lane >> 2;
    const int qc   = lane & 3;

    // phase 0: load F,G; store transposed bf16 hi/lo planes [w][h-pair]
    // thread: column w = tid&63, rows hb..hb+15 (coalesced gmem, c-free stores)
    {
        const int wcol = tid & 63;
        const int hb   = (tid >> 6) << 4;
        const float* Fc = F + wcol;
        const float* Gc = G + wcol;
#pragma unroll
        for (int hp = 0; hp < 8; hp++) {
            int h = hb + hp * 2;
            uint32_t hi, lo;
            bfsplit2(Fc[h * 64], Fc[(h + 1) * 64], hi, lo);
            sFtH[wcol * PLW + (h >> 1)] = hi;
            sFtL[wcol * PLW + (h >> 1)] = lo;
            bfsplit2(Gc[h * 64], Gc[(h + 1) * 64], hi, lo);
            sGtH[wcol * PLW + (h >> 1)] = hi;
            sGtL[wcol * PLW + (h >> 1)] = lo;
        }
    }
    __syncthreads();

    // GEMM1 (bf16x2, m16n8k16): S[w][v] = sum_h F[h][w] G[h][v]
    float acc[4][4];
#pragma unroll
    for (int nj = 0; nj < 4; nj++)
#pragma unroll
        for (int r = 0; r < 4; r++) acc[nj][r] = 0.f;

    const int wrow = mt * 16 + qr;
#pragma unroll
    for (int it = 0; it < 4; it++) {
        const int kp = it * 8 + qc;
        uint32_t aH[4], aL[4];
        aH[0] = sFtH[wrow * PLW + kp];       aH[1] = sFtH[(wrow + 8) * PLW + kp];
        aH[2] = sFtH[wrow * PLW + kp + 4];   aH[3] = sFtH[(wrow + 8) * PLW + kp + 4];
        aL[0] = sFtL[wrow * PLW + kp];       aL[1] = sFtL[(wrow + 8) * PLW + kp];
        aL[2] = sFtL[wrow * PLW + kp + 4];   aL[3] = sFtL[(wrow + 8) * PLW + kp + 4];
#pragma unroll
        for (int nj = 0; nj < 4; nj++) {
            const int v0 = nh * 32 + nj * 8 + qr;
            uint32_t bH[2], bL[2];
            bH[0] = sGtH[v0 * PLW + kp];  bH[1] = sGtH[v0 * PLW + kp + 4];
            bL[0] = sGtL[v0 * PLW + kp];  bL[1] = sGtL[v0 * PLW + kp + 4];
            mma_bf16(acc[nj], aH, bH);
            mma_bf16(acc[nj], aH, bL);
            mma_bf16(acc[nj], aL, bH);
        }
    }

    // split softmax (identical accumulator layout to m16n8k8)
    float mlo = -1e30f, mhi = -1e30f;
#pragma unroll
    for (int nj = 0; nj < 4; nj++) {
        mlo = fmaxf(mlo, fmaxf(acc[nj][0], acc[nj][1]));
        mhi = fmaxf(mhi, fmaxf(acc[nj][2], acc[nj][3]));
    }
    mlo = fmaxf(mlo, __shfl_xor_sync(0xffffffffu, mlo, 1));
    mlo = fmaxf(mlo, __shfl_xor_sync(0xffffffffu, mlo, 2));
    mhi = fmaxf(mhi, __shfl_xor_sync(0xffffffffu, mhi, 1));
    mhi = fmaxf(mhi, __shfl_xor_sync(0xffffffffu, mhi, 2));
    float slo = 0.f, shi = 0.f;
#pragma unroll
    for (int nj = 0; nj < 4; nj++) {
        acc[nj][0] = __expf(acc[nj][0] - mlo);
        acc[nj][1] = __expf(acc[nj][1] - mlo);
        acc[nj][2] = __expf(acc[nj][2] - mhi);
        acc[nj][3] = __expf(acc[nj][3] - mhi);
        slo += acc[nj][0] + acc[nj][1];
        shi += acc[nj][2] + acc[nj][3];
    }
    slo += __shfl_xor_sync(0xffffffffu, slo, 1);
    slo += __shfl_xor_sync(0xffffffffu, slo, 2);
    shi += __shfl_xor_sync(0xffffffffu, shi, 1);
    shi += __shfl_xor_sync(0xffffffffu, shi, 2);

    const int rlo = mt * 16 + qr, rhi = rlo + 8;
    if (qc == 0) {
        red[rlo * 4 + nh * 2]     = mlo;
        red[rlo * 4 + nh * 2 + 1] = slo;
        red[rhi * 4 + nh * 2]     = mhi;
        red[rhi * 4 + nh * 2 + 1] = shi;
    }
    __syncthreads();   // also: all GEMM1 plane reads complete

    float scl_lo, scl_hi;
    {
        float4 r4 = *(const float4*)&red[rlo * 4];
        float M = fmaxf(r4.x, r4.z);
        float den = r4.y * __expf(r4.x - M) + r4.w * __expf(r4.z - M);
        scl_lo = __expf(mlo - M) / den;
        r4 = *(const float4*)&red[rhi * 4];
        M = fmaxf(r4.x, r4.z);
        den = r4.y * __expf(r4.x - M) + r4.w * __expf(r4.z - M);
        scl_hi = __expf(mhi - M) / den;
    }

    // phase 2 staging (overlays phase-1 planes)
    uint32_t* sHmH = sm;
    uint32_t* sHmL = sm + PLSZ;
    uint32_t* sAtH = sm + 2 * PLSZ;
    uint32_t* sAtL = sm + 3 * PLSZ;

    // attn -> [v][w] scalar bf16 stores (hi/lo planes)
    {
        __nv_bfloat16* pH = (__nv_bfloat16*)sAtH;
        __nv_bfloat16* pL = (__nv_bfloat16*)sAtL;
        const int wlo = mt * 16 + qr, whi = wlo + 8;
#pragma unroll
        for (int nj = 0; nj < 4; nj++) {
            const int v = nh * 32 + nj * 8 + 2 * qc;
#pragma unroll
            for (int r = 0; r < 4; r++) {
                float val = acc[nj][r] * ((r < 2) ? scl_lo : scl_hi);
                int vv = v + (r & 1);
                int ww = (r < 2) ? wlo : whi;
                __nv_bfloat16 h = __float2bfloat16_rn(val);
                pH[vv * (PLW * 2) + ww] = h;
                pL[vv * (PLW * 2) + ww] = __float2bfloat16_rn(val - __bfloat162float(h));
            }
        }
    }
    // Hm -> [h][w-pair] packed hi/lo planes (natural rows, conflict-free)
#pragma unroll
    for (int it = 0; it < 4; it++) {
        int i = tid * 4 + it * 1024;
        int hr = i >> 6, w = i & 63;
        float4 v = *(const float4*)&Hm[i];
        uint32_t hiA, loA, hiB, loB;
        bfsplit2(v.x, v.y, hiA, loA);
        bfsplit2(v.z, v.w, hiB, loB);
        sHmH[hr * PLW + (w >> 1)]     = hiA;
        sHmH[hr * PLW + (w >> 1) + 1] = hiB;
        sHmL[hr * PLW + (w >> 1)]     = loA;
        sHmL[hr * PLW + (w >> 1) + 1] = loB;
    }
    __syncthreads();

    // GEMM2 (bf16x2): C[v][h] = sum_w attn[w][v] * Hm[h][w]  (= O^T)
#pragma unroll
    for (int nj = 0; nj < 4; nj++)
#pragma unroll
        for (int r = 0; r < 4; r++) acc[nj][r] = 0.f;

    const int vrow = mt * 16 + qr;
#pragma unroll
    for (int it = 0; it < 4; it++) {
        const int kp = it * 8 + qc;
        uint32_t aH[4], aL[4];
        aH[0] = sAtH[vrow * PLW + kp];       aH[1] = sAtH[(vrow + 8) * PLW + kp];
        aH[2] = sAtH[vrow * PLW + kp + 4];   aH[3] = sAtH[(vrow + 8) * PLW + kp + 4];
        aL[0] = sAtL[vrow * PLW + kp];       aL[1] = sAtL[(vrow + 8) * PLW + kp];
        aL[2] = sAtL[vrow * PLW + kp + 4];   aL[3] = sAtL[(vrow + 8) * PLW + kp + 4];
#pragma unroll
        for (int nj = 0; nj < 4; nj++) {
            const int hcol = nh * 32 + nj * 8 + qr;
            uint32_t bH[2], bL[2];
            bH[0] = sHmH[hcol * PLW + kp];  bH[1] = sHmH[hcol * PLW + kp + 4];
            bL[0] = sHmL[hcol * PLW + kp];  bL[1] = sHmL[hcol * PLW + kp + 4];
            mma_bf16(acc[nj], aH, bH);
            mma_bf16(acc[nj], aH, bL);
            mma_bf16(acc[nj], aL, bH);
        }
    }

    // store O[h][v] (tf32-rounded for the final conv)
    float* O = o + (size_t)bc * HW;
    const int vr = mt * 16 + qr;
#pragma unroll
    for (int nj = 0; nj < 4; nj++) {
        const int hc = nh * 32 + nj * 8 + 2 * qc;
        O[hc * 64 + vr]           = rtf(acc[nj][0]);
        O[(hc + 1) * 64 + vr]     = rtf(acc[nj][1]);
        O[hc * 64 + vr + 8]       = rtf(acc[nj][2]);
        O[(hc + 1) * 64 + vr + 8] = rtf(acc[nj][3]);
    }
}

// ---------------------------------------------------------------------------
extern "C" void kernel_launch(void* const* d_in, const int* in_sizes, int n_in,
                              void* d_out, int out_size) {
    const float* x  = (const float*)d_in[0];
    const float* wf = (const float*)d_in[1];
    const float* bf = (const float*)d_in[2];
    const float* wg = (const float*)d_in[3];
    const float* bg = (const float*)d_in[4];
    const float* wh = (const float*)d_in[5];
    const float* bh = (const float*)d_in[6];
    const float* wv = (const float*)d_in[7];
    const float* bv = (const float*)d_in[8];

    float *yb, *ob, *xrF, *wtF, *wtvF, *bcat;
    cudaGetSymbolAddress((void**)&yb,   g_y);
    cudaGetSymbolAddress((void**)&ob,   g_o);
    cudaGetSymbolAddress((void**)&xrF,  g_xrF);
    cudaGetSymbolAddress((void**)&wtF,  g_wtF);
    cudaGetSymbolAddress((void**)&wtvF, g_wtvF);
    cudaGetSymbolAddress((void**)&bcat, g_bcat);

    cudaFuncSetAttribute(conv_mma_kernel<true>,
                         cudaFuncAttributeMaxDynamicSharedMemorySize, CONV_SMEM);
    cudaFuncSetAttribute(conv_mma_kernel<false>,
                         cudaFuncAttributeMaxDynamicSharedMemorySize, CONV_SMEM);
    cudaFuncSetAttribute(attn_kernel,
                         cudaFuncAttributeMaxDynamicSharedMemorySize, ATT_SMEM);

    // 1) weights -> fragment layout; x -> fragment layout (tf32-rounded)
    prep_w_kernel<<<256, 256>>>(wf, wg, wh, wv, bf, bg, bh);
    x_frag_kernel<<<32768, 256>>>(x);

    // 2) fused f/g/h conv
    conv_mma_kernel<true><<<dim3(32, 6, 16), 256, CONV_SMEM>>>(xrF, wtF, bcat, yb);

    // 3) per-(b,c) attention
    attn_kernel<<<4096, 256, ATT_SMEM>>>(yb, ob);

    // 4) output conv
    conv_mma_kernel<false><<<dim3(32, 2, 16), 256, CONV_SMEM>>>(ob, wtvF, bv, (float*)d_out);
}

// round 10
// speedup vs baseline: 1.2973x; 1.0604x over previous
#include <cuda_runtime.h>
#include <cuda_bf16.h>
#include <math.h>
#include <stdint.h>

#define BATCH 16
#define HW    4096
#define CHW   1048576u

// Scratch (no allocation allowed -> __device__ globals)
__device__ float g_y[3ull * 16777216ull];   // fx, gx, hx
__device__ float g_o[16777216ull];          // attention output (tf32-rounded)
__device__ float g_xrF[16777216ull];        // x, tf32-rounded, B-fragment layout
__device__ float g_wtF[768 * 256];          // concat(wf,wg,wh), A-fragment layout
__device__ float g_wtvF[256 * 256];         // wv, A-fragment layout
__device__ float g_bcat[768];

__device__ __forceinline__ uint32_t f2tf32(float v) {
    uint32_t r;
    asm("cvt.rna.tf32.f32 %0, %1;" : "=r"(r) : "f"(v));
    return r;
}
__device__ __forceinline__ float rtf(float v) { return __uint_as_float(f2tf32(v)); }

__device__ __forceinline__ void mma_tf32(float* c, const uint32_t* a, const uint32_t* b) {
    asm volatile(
        "mma.sync.aligned.m16n8k8.row.col.f32.tf32.tf32.f32 "
        "{%0,%1,%2,%3}, {%4,%5,%6,%7}, {%8,%9}, {%0,%1,%2,%3};"
        : "+f"(c[0]), "+f"(c[1]), "+f"(c[2]), "+f"(c[3])
        : "r"(a[0]), "r"(a[1]), "r"(a[2]), "r"(a[3]), "r"(b[0]), "r"(b[1]));
}

__device__ __forceinline__ void mma_bf16(float* c, const uint32_t* a, const uint32_t* b) {
    asm volatile(
        "mma.sync.aligned.m16n8k16.row.col.f32.bf16.bf16.f32 "
        "{%0,%1,%2,%3}, {%4,%5,%6,%7}, {%8,%9}, {%0,%1,%2,%3};"
        : "+f"(c[0]), "+f"(c[1]), "+f"(c[2]), "+f"(c[3])
        : "r"(a[0]), "r"(a[1]), "r"(a[2]), "r"(a[3]), "r"(b[0]), "r"(b[1]));
}

// pack two f32 into bf16x2: low half = first arg, high = second
__device__ __forceinline__ uint32_t bfpack(float lo_elem, float hi_elem) {
    uint32_t r;
    asm("cvt.rn.bf16x2.f32 %0, %2, %1;" : "=r"(r) : "f"(lo_elem), "f"(hi_elem));
    return r;
}
__device__ __forceinline__ void bfsplit2(float x0, float x1, uint32_t& hi, uint32_t& lo) {
    hi = bfpack(x0, x1);
    float h0 = __uint_as_float(hi << 16);
    float h1 = __uint_as_float(hi & 0xffff0000u);
    lo = bfpack(x0 - h0, x1 - h1);
}

__device__ __forceinline__ void cpa16(uint32_t s, const void* g) {
    asm volatile("cp.async.cg.shared.global [%0], [%1], 16;" :: "r"(s), "l"(g));
}
#define CP_COMMIT()  asm volatile("cp.async.commit_group;" ::: "memory")
#define CP_WAIT2()   asm volatile("cp.async.wait_group 2;" ::: "memory")

#define LDSM4T(r0,r1,r2,r3,a) \
    asm volatile("ldmatrix.sync.aligned.m8n8.x4.trans.shared.b16 {%0,%1,%2,%3}, [%4];" \
                 : "=r"(r0),"=r"(r1),"=r"(r2),"=r"(r3) : "r"(a))
#define LDSM2T(r0,r1,a) \
    asm volatile("ldmatrix.sync.aligned.m8n8.x2.trans.shared.b16 {%0,%1}, [%2];" \
                 : "=r"(r0),"=r"(r1) : "r"(a))
#define LDSM4N(r0,r1,r2,r3,a) \
    asm volatile("ldmatrix.sync.aligned.m8n8.x4.shared.b16 {%0,%1,%2,%3}, [%4];" \
                 : "=r"(r0),"=r"(r1),"=r"(r2),"=r"(r3) : "r"(a))
#define LDSM2N(r0,r1,a) \
    asm volatile("ldmatrix.sync.aligned.m8n8.x2.shared.b16 {%0,%1}, [%2];" \
                 : "=r"(r0),"=r"(r1) : "r"(a))

// ---------------------------------------------------------------------------
// Prep: weights -> A-fragment layout, tf32-rounded; concat biases. (unchanged)
// ---------------------------------------------------------------------------
__global__ void prep_w_kernel(const float* __restrict__ wf, const float* __restrict__ wg,
                              const float* __restrict__ wh, const float* __restrict__ wv,
                              const float* __restrict__ bf, const float* __restrict__ bg,
                              const float* __restrict__ bh) {
    int idx = blockIdx.x * 256 + threadIdx.x;
    int lane = idx & 31;
    int t1 = idx >> 5;
    int mf = t1 & 7;  t1 >>= 3;
    int kk = t1 & 1;  t1 >>= 1;
    int ks = t1 & 15; t1 >>= 4;
    int qr = lane >> 2, qc = lane & 3;
    int k = ks * 16 + kk * 8 + qc;
    float4 v;
    if (idx < 49152) {
        int m = t1 * 128 + (mf >> 2) * 64 + (mf & 3) * 16 + qr;
        const float* w = (m < 256) ? wf : (m < 512) ? wg : wh;
        int mm = m & 255;
        v.x = rtf(w[mm * 256 + k]);
        v.y = rtf(w[(mm + 8) * 256 + k]);
        v.z = rtf(w[mm * 256 + k + 4]);
        v.w = rtf(w[(mm + 8) * 256 + k + 4]);
        *(float4*)&g_wtF[idx * 4] = v;
    } else {
        int idx2 = idx - 49152;
        int t2 = idx2 >> 5;
        int mf2 = t2 & 7;  t2 >>= 3;
        int kk2 = t2 & 1;  t2 >>= 1;
        int ks2 = t2 & 15; t2 >>= 4;
        int lane2 = idx2 & 31;
        int qr2 = lane2 >> 2, qc2 = lane2 & 3;
        int k2 = ks2 * 16 + kk2 * 8 + qc2;
        int m = t2 * 128 + (mf2 >> 2) * 64 + (mf2 & 3) * 16 + qr2;
        v.x = rtf(wv[m * 256 + k2]);
        v.y = rtf(wv[(m + 8) * 256 + k2]);
        v.z = rtf(wv[m * 256 + k2 + 4]);
        v.w = rtf(wv[(m + 8) * 256 + k2 + 4]);
        *(float4*)&g_wtvF[idx2 * 4] = v;
    }
    if (idx < 256) {
        g_bcat[idx]       = bf[idx];
        g_bcat[256 + idx] = bg[idx];
        g_bcat[512 + idx] = bh[idx];
    }
}

// x -> B-fragment layout, tf32-rounded (unchanged)
__global__ void x_frag_kernel(const float* __restrict__ x) {
    int idx = blockIdx.x * 256 + threadIdx.x;
    int lane = idx & 31;
    int t1 = idx >> 5;
    int nf = t1 & 15; t1 >>= 4;
    int kk = t1 & 1;  t1 >>= 1;
    int ks = t1 & 15; t1 >>= 4;
    int nt = t1 & 31; t1 >>= 5;
    int n = nt * 128 + (nf >> 2) * 32 + (nf & 3) * 8 + (lane >> 2);
    int k = ks * 16 + kk * 8 + (lane & 3);
    const float* xb = x + (size_t)t1 * CHW;
    float2 v;
    v.x = rtf(xb[(size_t)k * HW + n]);
    v.y = rtf(xb[(size_t)(k + 4) * HW + n]);
    *(float2*)&g_xrF[(size_t)idx * 2] = v;
}

// ---------------------------------------------------------------------------
// HMMA tf32 conv GEMM (unchanged from round 9)
// ---------------------------------------------------------------------------
#define SSTRIDE 136
#define SA(s)       ((s) * 2048)
#define SBF(s)      (8192 + (s) * 2048)
#define SBR(s, kr)  (8192 + (s) * 2176 + (kr) * SSTRIDE)
#define CONV_SMEM   ((8192 + 4 * 2176) * 4)

template <bool BFRAG>
__global__ __launch_bounds__(256, 2)
void conv_mma_kernel(const float* __restrict__ XB, const float* __restrict__ WTF,
                     const float* __restrict__ bias, float* __restrict__ Y) {
    extern __shared__ uint32_t dsm[];

    const int tid  = threadIdx.x;
    const int lane = tid & 31;
    const int warp = tid >> 5;
    const int mw   = warp >> 2;
    const int nw   = warp & 3;
    const int b    = blockIdx.z;
    const int nt   = blockIdx.x;
    const int n0   = nt * 128;
    const int mt   = blockIdx.y;
    const int m0   = mt * 128;

    const uint32_t sbase = (uint32_t)__cvta_generic_to_shared(dsm);
    const float* gA = WTF + (size_t)(mt * 16) * 2048;
    const float* gBF = XB + ((size_t)(b * 32 + nt) * 16) * 2048;
    const float* gBR = XB + (size_t)b * CHW + n0;

    float acc[4][4][4];
#pragma unroll
    for (int i = 0; i < 4; i++)
#pragma unroll
        for (int j = 0; j < 4; j++)
#pragma unroll
            for (int r = 0; r < 4; r++) acc[i][j][r] = 0.f;

    auto load_stage = [&](int s, int buf) {
#pragma unroll
        for (int h = 0; h < 2; h++) {
            int c = tid + h * 256;
            cpa16(sbase + (SA(buf) + c * 4) * 4, gA + (size_t)s * 2048 + c * 4);
            if (BFRAG) {
                cpa16(sbase + (SBF(buf) + c * 4) * 4, gBF + (size_t)s * 2048 + c * 4);
            } else {
                int kr = c >> 5, nc = (c & 31) * 4;
                cpa16(sbase + (SBR(buf, kr) + nc) * 4,
                      gBR + (size_t)(s * 16 + kr) * HW + nc);
            }
        }
    };

#pragma unroll
    for (int s = 0; s < 3; s++) { load_stage(s, s); CP_COMMIT(); }

    for (int kt = 0; kt < 16; kt++) {
        const int buf = kt & 3;
        CP_WAIT2();
        __syncthreads();

        if (kt < 13) load_stage(kt + 3, (kt + 3) & 3);
        CP_COMMIT();

#pragma unroll
        for (int kk = 0; kk < 2; kk++) {
            uint32_t af[4][4];
#pragma unroll
            for (int mi = 0; mi < 4; mi++) {
                const uint4 a4 = *(const uint4*)
                    &dsm[SA(buf) + ((kk * 8 + mw * 4 + mi) * 32 + lane) * 4];
                af[mi][0] = a4.x; af[mi][1] = a4.y; af[mi][2] = a4.z; af[mi][3] = a4.w;
            }
            uint32_t bfr[4][2];
            if (BFRAG) {
#pragma unroll
                for (int nj = 0; nj < 4; nj++) {
                    const uint2 b2 = *(const uint2*)
                        &dsm[SBF(buf) + ((kk * 16 + nw * 4 + nj) * 32 + lane) * 2];
                    bfr[nj][0] = b2.x; bfr[nj][1] = b2.y;
                }
            } else {
                const int qc = lane & 3, qr = lane >> 2;
                const uint32_t* B0 = dsm + SBR(buf, kk * 8 + qc) + nw * 32 + qr;
#pragma unroll
                for (int nj = 0; nj < 4; nj++) {
                    bfr[nj][0] = B0[nj * 8];
                    bfr[nj][1] = B0[4 * SSTRIDE + nj * 8];
                }
            }
#pragma unroll
            for (int mi = 0; mi < 4; mi++)
#pragma unroll
                for (int nj = 0; nj < 4; nj++)
                    mma_tf32(acc[mi][nj], af[mi], bfr[nj]);
        }
        __syncthreads();
    }

#pragma unroll
    for (int mi = 0; mi < 4; mi++) {
        int mr0 = m0 + mw * 64 + mi * 16 + (lane >> 2);
        float bv0 = bias[mr0];
        float bv1 = bias[mr0 + 8];
        float* y0 = Y + ((size_t)(mr0 >> 8) * BATCH + b) * CHW + (size_t)(mr0 & 255) * HW + n0;
        int mr1 = mr0 + 8;
        float* y1 = Y + ((size_t)(mr1 >> 8) * BATCH + b) * CHW + (size_t)(mr1 & 255) * HW + n0;
#pragma unroll
        for (int nj = 0; nj < 4; nj++) {
            int nc = nw * 32 + nj * 8 + 2 * (lane & 3);
            float2 v0 = make_float2(acc[mi][nj][0] + bv0, acc[mi][nj][1] + bv0);
            float2 v1 = make_float2(acc[mi][nj][2] + bv1, acc[mi][nj][3] + bv1);
            *(float2*)(y0 + nc) = v0;
            *(float2*)(y1 + nc) = v1;
        }
    }
}

// ---------------------------------------------------------------------------
// Fused attention, bf16x2 split + ldmatrix operand paths. 256 threads, 8 warps.
//   warp w -> m-tile (w>>1) [16 rows], n-half (w&1) [32 cols]
// All planes natural layout, row stride WS=36 words (64 bf16 + 8 pad):
//   phase1: Fh@0 Fl@PL Gh@2PL Gl@3PL  ([h][w] bf16)   -> GEMM1 via ldmatrix.trans
//   phase2: HmH@0 HmL@PL AtH@2PL AtL@3PL ([h][w]/[v][w]) -> GEMM2 via ldmatrix
//   red (f32) @4PL.  Stride 36 == 4 mod 8 -> ldmatrix 8-row phases conflict-free.
// ---------------------------------------------------------------------------
#define WS   36
#define PL   2304
#define ATT_SMEM 37888

__global__ __launch_bounds__(256)
void attn_kernel(const float* __restrict__ y, float* __restrict__ o) {
    extern __shared__ uint32_t sm[];
    const int bc = blockIdx.x;
    const size_t BCHW = (size_t)BATCH * CHW;
    const float* F  = y + (size_t)bc * HW;
    const float* G  = y + BCHW + (size_t)bc * HW;
    const float* Hm = y + 2 * BCHW + (size_t)bc * HW;

    uint32_t* sFh = sm;
    uint32_t* sFl = sm + PL;
    uint32_t* sGh = sm + 2 * PL;
    uint32_t* sGl = sm + 3 * PL;
    float*    red = (float*)(sm + 4 * PL);   // [64][4]

    const uint32_t sb = (uint32_t)__cvta_generic_to_shared(sm);
    const int tid  = threadIdx.x;
    const int lane = tid & 31;
    const int warp = tid >> 5;
    const int mt   = warp >> 1;
    const int nh   = warp & 1;
    const int qr   = lane >> 2;
    const int qc   = lane & 3;

    // phase 0: F,G natural [h][w], bf16 hi/lo planes, fully vectorized
#pragma unroll
    for (int it = 0; it < 4; it++) {
        int i = tid * 4 + it * 1024;
        int off = (i >> 6) * WS + ((i & 63) >> 1);
        float4 f = *(const float4*)&F[i];
        float4 g = *(const float4*)&G[i];
        uint32_t hA, lA, hB, lB;
        bfsplit2(f.x, f.y, hA, lA); bfsplit2(f.z, f.w, hB, lB);
        *(uint2*)&sFh[off] = make_uint2(hA, hB);
        *(uint2*)&sFl[off] = make_uint2(lA, lB);
        bfsplit2(g.x, g.y, hA, lA); bfsplit2(g.z, g.w, hB, lB);
        *(uint2*)&sGh[off] = make_uint2(hA, hB);
        *(uint2*)&sGl[off] = make_uint2(lA, lB);
    }
    __syncthreads();

    // GEMM1 (bf16x2): S[w][v] = sum_h F[h][w] G[h][v]; operands via ldmatrix.trans
    float acc[4][4];
#pragma unroll
    for (int nj = 0; nj < 4; nj++)
#pragma unroll
        for (int r = 0; r < 4; r++) acc[nj][r] = 0.f;

    const int kselA = (lane & 7) + 8 * ((lane >> 4) & 1);   // A: x4.trans row select
    const int mcolA = mt * 16 + 8 * ((lane >> 3) & 1);      // A: column base
    const int kselB = (lane & 7) + 8 * ((lane >> 3) & 1);   // B: x2.trans row select
#pragma unroll
    for (int it = 0; it < 4; it++) {
        uint32_t aaddr = sb + ((it * 16 + kselA) * WS) * 4 + mcolA * 2;
        uint32_t aH[4], aL[4];
        LDSM4T(aH[0], aH[1], aH[2], aH[3], aaddr);
        LDSM4T(aL[0], aL[1], aL[2], aL[3], aaddr + PL * 4);
        uint32_t bbase = sb + 2 * PL * 4 + ((it * 16 + kselB) * WS) * 4 + (nh * 32) * 2;
#pragma unroll
        for (int nj = 0; nj < 4; nj++) {
            uint32_t bH[2], bL[2];
            LDSM2T(bH[0], bH[1], bbase + nj * 16);
            LDSM2T(bL[0], bL[1], bbase + nj * 16 + PL * 4);
            mma_bf16(acc[nj], aH, bH);
            mma_bf16(acc[nj], aH, bL);
            mma_bf16(acc[nj], aL, bH);
        }
    }

    // split softmax
    float mlo = -1e30f, mhi = -1e30f;
#pragma unroll
    for (int nj = 0; nj < 4; nj++) {
        mlo = fmaxf(mlo, fmaxf(acc[nj][0], acc[nj][1]));
        mhi = fmaxf(mhi, fmaxf(acc[nj][2], acc[nj][3]));
    }
    mlo = fmaxf(mlo, __shfl_xor_sync(0xffffffffu, mlo, 1));
    mlo = fmaxf(mlo, __shfl_xor_sync(0xffffffffu, mlo, 2));
    mhi = fmaxf(mhi, __shfl_xor_sync(0xffffffffu, mhi, 1));
    mhi = fmaxf(mhi, __shfl_xor_sync(0xffffffffu, mhi, 2));
    float slo = 0.f, shi = 0.f;
#pragma unroll
    for (int nj = 0; nj < 4; nj++) {
        acc[nj][0] = __expf(acc[nj][0] - mlo);
        acc[nj][1] = __expf(acc[nj][1] - mlo);
        acc[nj][2] = __expf(acc[nj][2] - mhi);
        acc[nj][3] = __expf(acc[nj][3] - mhi);
        slo += acc[nj][0] + acc[nj][1];
        shi += acc[nj][2] + acc[nj][3];
    }
    slo += __shfl_xor_sync(0xffffffffu, slo, 1);
    slo += __shfl_xor_sync(0xffffffffu, slo, 2);
    shi += __shfl_xor_sync(0xffffffffu, shi, 1);
    shi += __shfl_xor_sync(0xffffffffu, shi, 2);

    const int rlo = mt * 16 + qr, rhi = rlo + 8;
    if (qc == 0) {
        red[rlo * 4 + nh * 2]     = mlo;
        red[rlo * 4 + nh * 2 + 1] = slo;
        red[rhi * 4 + nh * 2]     = mhi;
        red[rhi * 4 + nh * 2 + 1] = shi;
    }
    __syncthreads();   // also: all GEMM1 plane reads complete

    float scl_lo, scl_hi;
    {
        float4 r4 = *(const float4*)&red[rlo * 4];
        float M = fmaxf(r4.x, r4.z);
        float den = r4.y * __expf(r4.x - M) + r4.w * __expf(r4.z - M);
        scl_lo = __expf(mlo - M) / den;
        r4 = *(const float4*)&red[rhi * 4];
        M = fmaxf(r4.x, r4.z);
        den = r4.y * __expf(r4.x - M) + r4.w * __expf(r4.z - M);
        scl_hi = __expf(mhi - M) / den;
    }

    // phase 2 staging (overlays phase-1 planes; red region untouched)
    uint32_t* sHmH = sm;
    uint32_t* sHmL = sm + PL;
    uint32_t* sAtH = sm + 2 * PL;
    uint32_t* sAtL = sm + 3 * PL;

    // attn -> [v][w] scalar bf16 hi/lo
    {
        __nv_bfloat16* pH = (__nv_bfloat16*)sAtH;
        __nv_bfloat16* pL = (__nv_bfloat16*)sAtL;
        const int wlo = mt * 16 + qr, whi = wlo + 8;
#pragma unroll
        for (int nj = 0; nj < 4; nj++) {
            const int v = nh * 32 + nj * 8 + 2 * qc;
#pragma unroll
            for (int r = 0; r < 4; r++) {
                float val = acc[nj][r] * ((r < 2) ? scl_lo : scl_hi);
                int vv = v + (r & 1);
                int ww = (r < 2) ? wlo : whi;
                __nv_bfloat16 h = __float2bfloat16_rn(val);
                pH[vv * (WS * 2) + ww] = h;
                pL[vv * (WS * 2) + ww] = __float2bfloat16_rn(val - __bfloat162float(h));
            }
        }
    }
    // Hm -> natural [h][w] hi/lo planes, vectorized
#pragma unroll
    for (int it = 0; it < 4; it++) {
        int i = tid * 4 + it * 1024;
        int off = (i >> 6) * WS + ((i & 63) >> 1);
        float4 v = *(const float4*)&Hm[i];
        uint32_t hA, lA, hB, lB;
        bfsplit2(v.x, v.y, hA, lA); bfsplit2(v.z, v.w, hB, lB);
        *(uint2*)&sHmH[off] = make_uint2(hA, hB);
        *(uint2*)&sHmL[off] = make_uint2(lA, lB);
    }
    __syncthreads();

    // GEMM2 (bf16x2): C[v][h] = sum_w attn[w][v] * Hm[h][w]  (= O^T), ldmatrix non-trans
#pragma unroll
    for (int nj = 0; nj < 4; nj++)
#pragma unroll
        for (int r = 0; r < 4; r++) acc[nj][r] = 0.f;

    const int mrowA2 = mt * 16 + (lane & 7) + 8 * ((lane >> 3) & 1);
    const int kcolA2 = 8 * ((lane >> 4) & 1);
    const int nrowB2 = nh * 32 + (lane & 7);
    const int kcolB2 = 8 * ((lane >> 3) & 1);
#pragma unroll
    for (int it = 0; it < 4; it++) {
        uint32_t aaddr = sb + 2 * PL * 4 + (mrowA2 * WS) * 4 + (it * 16 + kcolA2) * 2;
        uint32_t aH[4], aL[4];
        LDSM4N(aH[0], aH[1], aH[2], aH[3], aaddr);
        LDSM4N(aL[0], aL[1], aL[2], aL[3], aaddr + PL * 4);
#pragma unroll
        for (int nj = 0; nj < 4; nj++) {
            uint32_t baddr = sb + ((nrowB2 + nj * 8) * WS) * 4 + (it * 16 + kcolB2) * 2;
            uint32_t bH[2], bL[2];
            LDSM2N(bH[0], bH[1], baddr);
            LDSM2N(bL[0], bL[1], baddr + PL * 4);
            mma_bf16(acc[nj], aH, bH);
            mma_bf16(acc[nj], aH, bL);
            mma_bf16(acc[nj], aL, bH);
        }
    }

    // store O[h][v] (tf32-rounded for the final conv)
    float* O = o + (size_t)bc * HW;
    const int vr = mt * 16 + qr;
#pragma unroll
    for (int nj = 0; nj < 4; nj++) {
        const int hc = nh * 32 + nj * 8 + 2 * qc;
        O[hc * 64 + vr]           = rtf(acc[nj][0]);
        O[(hc + 1) * 64 + vr]     = rtf(acc[nj][1]);
        O[hc * 64 + vr + 8]       = rtf(acc[nj][2]);
        O[(hc + 1) * 64 + vr + 8] = rtf(acc[nj][3]);
    }
}

// ---------------------------------------------------------------------------
extern "C" void kernel_launch(void* const* d_in, const int* in_sizes, int n_in,
                              void* d_out, int out_size) {
    const float* x  = (const float*)d_in[0];
    const float* wf = (const float*)d_in[1];
    const float* bf = (const float*)d_in[2];
    const float* wg = (const float*)d_in[3];
    const float* bg = (const float*)d_in[4];
    const float* wh = (const float*)d_in[5];
    const float* bh = (const float*)d_in[6];
    const float* wv = (const float*)d_in[7];
    const float* bv = (const float*)d_in[8];

    float *yb, *ob, *xrF, *wtF, *wtvF, *bcat;
    cudaGetSymbolAddress((void**)&yb,   g_y);
    cudaGetSymbolAddress((void**)&ob,   g_o);
    cudaGetSymbolAddress((void**)&xrF,  g_xrF);
    cudaGetSymbolAddress((void**)&wtF,  g_wtF);
    cudaGetSymbolAddress((void**)&wtvF, g_wtvF);
    cudaGetSymbolAddress((void**)&bcat, g_bcat);

    cudaFuncSetAttribute(conv_mma_kernel<true>,
                         cudaFuncAttributeMaxDynamicSharedMemorySize, CONV_SMEM);
    cudaFuncSetAttribute(conv_mma_kernel<false>,
                         cudaFuncAttributeMaxDynamicSharedMemorySize, CONV_SMEM);
    cudaFuncSetAttribute(attn_kernel,
                         cudaFuncAttributeMaxDynamicSharedMemorySize, ATT_SMEM);

    // 1) weights -> fragment layout; x -> fragment layout (tf32-rounded)
    prep_w_kernel<<<256, 256>>>(wf, wg, wh, wv, bf, bg, bh);
    x_frag_kernel<<<32768, 256>>>(x);

    // 2) fused f/g/h conv
    conv_mma_kernel<true><<<dim3(32, 6, 16), 256, CONV_SMEM>>>(xrF, wtF, bcat, yb);

    // 3) per-(b,c) attention
    attn_kernel<<<4096, 256, ATT_SMEM>>>(yb, ob);

    // 4) output conv
    conv_mma_kernel<false><<<dim3(32, 2, 16), 256, CONV_SMEM>>>(ob, wtvF, bv, (float*)d_out);
}

// round 12
// speedup vs baseline: 1.3070x; 1.0075x over previous
#include <cuda_runtime.h>
#include <cuda_bf16.h>
#include <math.h>
#include <stdint.h>

#define BATCH 16
#define HW    4096
#define CHW   1048576u

// Scratch (no allocation allowed -> __device__ globals)
__device__ float g_y[3ull * 16777216ull];   // fx, gx, hx
__device__ float g_o[16777216ull];          // attention output (tf32-rounded)
__device__ float g_xrF[16777216ull];        // x, tf32-rounded, B-fragment layout
__device__ float g_wtF[768 * 256];          // concat(wf,wg,wh), A-fragment layout
__device__ float g_wtvF[256 * 256];         // wv, A-fragment layout
__device__ float g_bcat[768];

__device__ __forceinline__ uint32_t f2tf32(float v) {
    uint32_t r;
    asm("cvt.rna.tf32.f32 %0, %1;" : "=r"(r) : "f"(v));
    return r;
}
__device__ __forceinline__ float rtf(float v) { return __uint_as_float(f2tf32(v)); }

__device__ __forceinline__ void mma_tf32(float* c, const uint32_t* a, const uint32_t* b) {
    asm volatile(
        "mma.sync.aligned.m16n8k8.row.col.f32.tf32.tf32.f32 "
        "{%0,%1,%2,%3}, {%4,%5,%6,%7}, {%8,%9}, {%0,%1,%2,%3};"
        : "+f"(c[0]), "+f"(c[1]), "+f"(c[2]), "+f"(c[3])
        : "r"(a[0]), "r"(a[1]), "r"(a[2]), "r"(a[3]), "r"(b[0]), "r"(b[1]));
}

__device__ __forceinline__ void mma_bf16(float* c, const uint32_t* a, const uint32_t* b) {
    asm volatile(
        "mma.sync.aligned.m16n8k16.row.col.f32.bf16.bf16.f32 "
        "{%0,%1,%2,%3}, {%4,%5,%6,%7}, {%8,%9}, {%0,%1,%2,%3};"
        : "+f"(c[0]), "+f"(c[1]), "+f"(c[2]), "+f"(c[3])
        : "r"(a[0]), "r"(a[1]), "r"(a[2]), "r"(a[3]), "r"(b[0]), "r"(b[1]));
}

// pack two f32 into bf16x2: low half = first arg, high = second
__device__ __forceinline__ uint32_t bfpack(float lo_elem, float hi_elem) {
    uint32_t r;
    asm("cvt.rn.bf16x2.f32 %0, %2, %1;" : "=r"(r) : "f"(lo_elem), "f"(hi_elem));
    return r;
}
__device__ __forceinline__ void bfsplit2(float x0, float x1, uint32_t& hi, uint32_t& lo) {
    hi = bfpack(x0, x1);
    float h0 = __uint_as_float(hi << 16);
    float h1 = __uint_as_float(hi & 0xffff0000u);
    lo = bfpack(x0 - h0, x1 - h1);
}

__device__ __forceinline__ void cpa16(uint32_t s, const void* g) {
    asm volatile("cp.async.cg.shared.global [%0], [%1], 16;" :: "r"(s), "l"(g));
}
#define CP_COMMIT()  asm volatile("cp.async.commit_group;" ::: "memory")
#define CP_WAIT3()   asm volatile("cp.async.wait_group 3;" ::: "memory")
#define CP_WAIT0()   asm volatile("cp.async.wait_group 0;" ::: "memory")

#define LDSM4T(r0,r1,r2,r3,a) \
    asm volatile("ldmatrix.sync.aligned.m8n8.x4.trans.shared.b16 {%0,%1,%2,%3}, [%4];" \
                 : "=r"(r0),"=r"(r1),"=r"(r2),"=r"(r3) : "r"(a))
#define LDSM2T(r0,r1,a) \
    asm volatile("ldmatrix.sync.aligned.m8n8.x2.trans.shared.b16 {%0,%1}, [%2];" \
                 : "=r"(r0),"=r"(r1) : "r"(a))
#define LDSM4N(r0,r1,r2,r3,a) \
    asm volatile("ldmatrix.sync.aligned.m8n8.x4.shared.b16 {%0,%1,%2,%3}, [%4];" \
                 : "=r"(r0),"=r"(r1),"=r"(r2),"=r"(r3) : "r"(a))
#define LDSM2N(r0,r1,a) \
    asm volatile("ldmatrix.sync.aligned.m8n8.x2.shared.b16 {%0,%1}, [%2];" \
                 : "=r"(r0),"=r"(r1) : "r"(a))

// ---------------------------------------------------------------------------
// Prep: weights -> A-fragment layout, tf32-rounded; concat biases. (unchanged)
// ---------------------------------------------------------------------------
__global__ void prep_w_kernel(const float* __restrict__ wf, const float* __restrict__ wg,
                              const float* __restrict__ wh, const float* __restrict__ wv,
                              const float* __restrict__ bf, const float* __restrict__ bg,
                              const float* __restrict__ bh) {
    int idx = blockIdx.x * 256 + threadIdx.x;
    int lane = idx & 31;
    int t1 = idx >> 5;
    int mf = t1 & 7;  t1 >>= 3;
    int kk = t1 & 1;  t1 >>= 1;
    int ks = t1 & 15; t1 >>= 4;
    int qr = lane >> 2, qc = lane & 3;
    int k = ks * 16 + kk * 8 + qc;
    float4 v;
    if (idx < 49152) {
        int m = t1 * 128 + (mf >> 2) * 64 + (mf & 3) * 16 + qr;
        const float* w = (m < 256) ? wf : (m < 512) ? wg : wh;
        int mm = m & 255;
        v.x = rtf(w[mm * 256 + k]);
        v.y = rtf(w[(mm + 8) * 256 + k]);
        v.z = rtf(w[mm * 256 + k + 4]);
        v.w = rtf(w[(mm + 8) * 256 + k + 4]);
        *(float4*)&g_wtF[idx * 4] = v;
    } else {
        int idx2 = idx - 49152;
        int t2 = idx2 >> 5;
        int mf2 = t2 & 7;  t2 >>= 3;
        int kk2 = t2 & 1;  t2 >>= 1;
        int ks2 = t2 & 15; t2 >>= 4;
        int lane2 = idx2 & 31;
        int qr2 = lane2 >> 2, qc2 = lane2 & 3;
        int k2 = ks2 * 16 + kk2 * 8 + qc2;
        int m = t2 * 128 + (mf2 >> 2) * 64 + (mf2 & 3) * 16 + qr2;
        v.x = rtf(wv[m * 256 + k2]);
        v.y = rtf(wv[(m + 8) * 256 + k2]);
        v.z = rtf(wv[m * 256 + k2 + 4]);
        v.w = rtf(wv[(m + 8) * 256 + k2 + 4]);
        *(float4*)&g_wtvF[idx2 * 4] = v;
    }
    if (idx < 256) {
        g_bcat[idx]       = bf[idx];
        g_bcat[256 + idx] = bg[idx];
        g_bcat[512 + idx] = bh[idx];
    }
}

// x -> B-fragment layout, tf32-rounded (unchanged)
__global__ void x_frag_kernel(const float* __restrict__ x) {
    int idx = blockIdx.x * 256 + threadIdx.x;
    int lane = idx & 31;
    int t1 = idx >> 5;
    int nf = t1 & 15; t1 >>= 4;
    int kk = t1 & 1;  t1 >>= 1;
    int ks = t1 & 15; t1 >>= 4;
    int nt = t1 & 31; t1 >>= 5;
    int n = nt * 128 + (nf >> 2) * 32 + (nf & 3) * 8 + (lane >> 2);
    int k = ks * 16 + kk * 8 + (lane & 3);
    const float* xb = x + (size_t)t1 * CHW;
    float2 v;
    v.x = rtf(xb[(size_t)k * HW + n]);
    v.y = rtf(xb[(size_t)(k + 4) * HW + n]);
    *(float2*)&g_xrF[(size_t)idx * 2] = v;
}

// ---------------------------------------------------------------------------
// HMMA tf32 conv GEMM. 5-stage cp.async ring, ONE barrier per k-tile with the
// CORRECT ordering: issue(kt+3) -> commit -> wait3 -> __syncthreads -> compute(kt).
//   RAW: wait3 retires each thread's own stage-kt copies; the barrier then
//        publishes them to all threads (wait BEFORE sync — round-11's bug was
//        sync before wait, which only covers the thread's own data).
//   WAR: issue(kt+3) writes buf (kt+3)%5 = (kt-2)%5, last read by
//        compute(kt-2); iteration kt-1's barrier separates them.
// ---------------------------------------------------------------------------
#define SSTRIDE 136
#define SA(s)       ((s) * 2048)
#define SBF(s)      (10240 + (s) * 2048)
#define SBR(s, kr)  (10240 + (s) * 2176 + (kr) * SSTRIDE)
#define CONV_SMEM   ((10240 + 5 * 2176) * 4)   // 84480 B

template <bool BFRAG>
__global__ __launch_bounds__(256, 2)
void conv_mma_kernel(const float* __restrict__ XB, const float* __restrict__ WTF,
                     const float* __restrict__ bias, float* __restrict__ Y) {
    extern __shared__ uint32_t dsm[];

    const int tid  = threadIdx.x;
    const int lane = tid & 31;
    const int warp = tid >> 5;
    const int mw   = warp >> 2;
    const int nw   = warp & 3;
    const int b    = blockIdx.z;
    const int nt   = blockIdx.x;
    const int n0   = nt * 128;
    const int mt   = blockIdx.y;
    const int m0   = mt * 128;

    const uint32_t sbase = (uint32_t)__cvta_generic_to_shared(dsm);
    const float* gA = WTF + (size_t)(mt * 16) * 2048;
    const float* gBF = XB + ((size_t)(b * 32 + nt) * 16) * 2048;
    const float* gBR = XB + (size_t)b * CHW + n0;

    float acc[4][4][4];
#pragma unroll
    for (int i = 0; i < 4; i++)
#pragma unroll
        for (int j = 0; j < 4; j++)
#pragma unroll
            for (int r = 0; r < 4; r++) acc[i][j][r] = 0.f;

    auto load_stage = [&](int s, int buf) {
#pragma unroll
        for (int h = 0; h < 2; h++) {
            int c = tid + h * 256;
            cpa16(sbase + (SA(buf) + c * 4) * 4, gA + (size_t)s * 2048 + c * 4);
            if (BFRAG) {
                cpa16(sbase + (SBF(buf) + c * 4) * 4, gBF + (size_t)s * 2048 + c * 4);
            } else {
                int kr = c >> 5, nc = (c & 31) * 4;
                cpa16(sbase + (SBR(buf, kr) + nc) * 4,
                      gBR + (size_t)(s * 16 + kr) * HW + nc);
            }
        }
    };

    // prologue: stages 0..2 into buffers 0..2
#pragma unroll
    for (int s = 0; s < 3; s++) { load_stage(s, s); CP_COMMIT(); }

    int buf = 0, nbuf = 3;   // compute buffer (kt%5), issue buffer ((kt+3)%5)
    for (int kt = 0; kt < 16; kt++) {
        if (kt < 13) load_stage(kt + 3, nbuf);
        CP_COMMIT();
        CP_WAIT3();          // own stage-kt copies retired
        __syncthreads();     // publish everyone's stage kt; fences WAR for kt+1's issue

#pragma unroll
        for (int kk = 0; kk < 2; kk++) {
            uint32_t af[4][4];
#pragma unroll
            for (int mi = 0; mi < 4; mi++) {
                const uint4 a4 = *(const uint4*)
                    &dsm[SA(buf) + ((kk * 8 + mw * 4 + mi) * 32 + lane) * 4];
                af[mi][0] = a4.x; af[mi][1] = a4.y; af[mi][2] = a4.z; af[mi][3] = a4.w;
            }
            uint32_t bfr[4][2];
            if (BFRAG) {
#pragma unroll
                for (int nj = 0; nj < 4; nj++) {
                    const uint2 b2 = *(const uint2*)
                        &dsm[SBF(buf) + ((kk * 16 + nw * 4 + nj) * 32 + lane) * 2];
                    bfr[nj][0] = b2.x; bfr[nj][1] = b2.y;
                }
            } else {
                const int qc = lane & 3, qr = lane >> 2;
                const uint32_t* B0 = dsm + SBR(buf, kk * 8 + qc) + nw * 32 + qr;
#pragma unroll
                for (int nj = 0; nj < 4; nj++) {
                    bfr[nj][0] = B0[nj * 8];
                    bfr[nj][1] = B0[4 * SSTRIDE + nj * 8];
                }
            }
#pragma unroll
            for (int mi = 0; mi < 4; mi++)
#pragma unroll
                for (int nj = 0; nj < 4; nj++)
                    mma_tf32(acc[mi][nj], af[mi], bfr[nj]);
        }
        if (++buf == 5)  buf = 0;
        if (++nbuf == 5) nbuf = 0;
    }

#pragma unroll
    for (int mi = 0; mi < 4; mi++) {
        int mr0 = m0 + mw * 64 + mi * 16 + (lane >> 2);
        float bv0 = bias[mr0];
        float bv1 = bias[mr0 + 8];
        float* y0 = Y + ((size_t)(mr0 >> 8) * BATCH + b) * CHW + (size_t)(mr0 & 255) * HW + n0;
        int mr1 = mr0 + 8;
        float* y1 = Y + ((size_t)(mr1 >> 8) * BATCH + b) * CHW + (size_t)(mr1 & 255) * HW + n0;
#pragma unroll
        for (int nj = 0; nj < 4; nj++) {
            int nc = nw * 32 + nj * 8 + 2 * (lane & 3);
            float2 v0 = make_float2(acc[mi][nj][0] + bv0, acc[mi][nj][1] + bv0);
            float2 v1 = make_float2(acc[mi][nj][2] + bv1, acc[mi][nj][3] + bv1);
            *(float2*)(y0 + nc) = v0;
            *(float2*)(y1 + nc) = v1;
        }
    }
}

// ---------------------------------------------------------------------------
// Fused attention, bf16x2 split + ldmatrix + cp.async Hm prefetch.
// Hm prefetch is per-thread self-consistent: each thread reads from HmRaw
// exactly the words it copied, after its own wait_group 0 (valid per PTX).
// ---------------------------------------------------------------------------
#define WS   36
#define PL   2304
#define ATT_SMEM 54272

__global__ __launch_bounds__(256)
void attn_kernel(const float* __restrict__ y, float* __restrict__ o) {
    extern __shared__ uint32_t sm[];
    const int bc = blockIdx.x;
    const size_t BCHW = (size_t)BATCH * CHW;
    const float* F  = y + (size_t)bc * HW;
    const float* G  = y + BCHW + (size_t)bc * HW;
    const float* Hm = y + 2 * BCHW + (size_t)bc * HW;

    uint32_t* sFh = sm;
    uint32_t* sFl = sm + PL;
    uint32_t* sGh = sm + 2 * PL;
    uint32_t* sGl = sm + 3 * PL;
    float*    red = (float*)(sm + 4 * PL);        // [64][4]
    float*  HmRaw = (float*)(sm + 4 * PL + 256);  // [4096] f32

    const uint32_t sb = (uint32_t)__cvta_generic_to_shared(sm);
    const int tid  = threadIdx.x;
    const int lane = tid & 31;
    const int warp = tid >> 5;
    const int mt   = warp >> 1;
    const int nh   = warp & 1;
    const int qr   = lane >> 2;
    const int qc   = lane & 3;

    // prefetch Hm into smem (overlaps GEMM1 + softmax)
#pragma unroll
    for (int it = 0; it < 4; it++)
        cpa16(sb + 37888 + tid * 16 + it * 4096, Hm + tid * 4 + it * 1024);
    CP_COMMIT();

    // phase 0: F,G natural [h][w], bf16 hi/lo planes, fully vectorized
#pragma unroll
    for (int it = 0; it < 4; it++) {
        int i = tid * 4 + it * 1024;
        int off = (i >> 6) * WS + ((i & 63) >> 1);
        float4 f = *(const float4*)&F[i];
        float4 g = *(const float4*)&G[i];
        uint32_t hA, lA, hB, lB;
        bfsplit2(f.x, f.y, hA, lA); bfsplit2(f.z, f.w, hB, lB);
        *(uint2*)&sFh[off] = make_uint2(hA, hB);
        *(uint2*)&sFl[off] = make_uint2(lA, lB);
        bfsplit2(g.x, g.y, hA, lA); bfsplit2(g.z, g.w, hB, lB);
        *(uint2*)&sGh[off] = make_uint2(hA, hB);
        *(uint2*)&sGl[off] = make_uint2(lA, lB);
    }
    __syncthreads();

    // GEMM1 (bf16x2): S[w][v] = sum_h F[h][w] G[h][v]; operands via ldmatrix.trans
    float acc[4][4];
#pragma unroll
    for (int nj = 0; nj < 4; nj++)
#pragma unroll
        for (int r = 0; r < 4; r++) acc[nj][r] = 0.f;

    const int kselA = (lane & 7) + 8 * ((lane >> 4) & 1);
    const int mcolA = mt * 16 + 8 * ((lane >> 3) & 1);
    const int kselB = (lane & 7) + 8 * ((lane >> 3) & 1);
#pragma unroll
    for (int it = 0; it < 4; it++) {
        uint32_t aaddr = sb + ((it * 16 + kselA) * WS) * 4 + mcolA * 2;
        uint32_t aH[4], aL[4];
        LDSM4T(aH[0], aH[1], aH[2], aH[3], aaddr);
        LDSM4T(aL[0], aL[1], aL[2], aL[3], aaddr + PL * 4);
        uint32_t bbase = sb + 2 * PL * 4 + ((it * 16 + kselB) * WS) * 4 + (nh * 32) * 2;
#pragma unroll
        for (int nj = 0; nj < 4; nj++) {
            uint32_t bH[2], bL[2];
            LDSM2T(bH[0], bH[1], bbase + nj * 16);
            LDSM2T(bL[0], bL[1], bbase + nj * 16 + PL * 4);
            mma_bf16(acc[nj], aH, bH);
            mma_bf16(acc[nj], aH, bL);
            mma_bf16(acc[nj], aL, bH);
        }
    }

    // split softmax
    float mlo = -1e30f, mhi = -1e30f;
#pragma unroll
    for (int nj = 0; nj < 4; nj++) {
        mlo = fmaxf(mlo, fmaxf(acc[nj][0], acc[nj][1]));
        mhi = fmaxf(mhi, fmaxf(acc[nj][2], acc[nj][3]));
    }
    mlo = fmaxf(mlo, __shfl_xor_sync(0xffffffffu, mlo, 1));
    mlo = fmaxf(mlo, __shfl_xor_sync(0xffffffffu, mlo, 2));
    mhi = fmaxf(mhi, __shfl_xor_sync(0xffffffffu, mhi, 1));
    mhi = fmaxf(mhi, __shfl_xor_sync(0xffffffffu, mhi, 2));
    float slo = 0.f, shi = 0.f;
#pragma unroll
    for (int nj = 0; nj < 4; nj++) {
        acc[nj][0] = __expf(acc[nj][0] - mlo);
        acc[nj][1] = __expf(acc[nj][1] - mlo);
        acc[nj][2] = __expf(acc[nj][2] - mhi);
        acc[nj][3] = __expf(acc[nj][3] - mhi);
        slo += acc[nj][0] + acc[nj][1];
        shi += acc[nj][2] + acc[nj][3];
    }
    slo += __shfl_xor_sync(0xffffffffu, slo, 1);
    slo += __shfl_xor_sync(0xffffffffu, slo, 2);
    shi += __shfl_xor_sync(0xffffffffu, shi, 1);
    shi += __shfl_xor_sync(0xffffffffu, shi, 2);

    const int rlo = mt * 16 + qr, rhi = rlo + 8;
    if (qc == 0) {
        red[rlo * 4 + nh * 2]     = mlo;
        red[rlo * 4 + nh * 2 + 1] = slo;
        red[rhi * 4 + nh * 2]     = mhi;
        red[rhi * 4 + nh * 2 + 1] = shi;
    }
    __syncthreads();   // also: all GEMM1 plane reads complete

    float scl_lo, scl_hi;
    {
        float4 r4 = *(const float4*)&red[rlo * 4];
        float M = fmaxf(r4.x, r4.z);
        float den = r4.y * __expf(r4.x - M) + r4.w * __expf(r4.z - M);
        scl_lo = __expf(mlo - M) / den;
        r4 = *(const float4*)&red[rhi * 4];
        M = fmaxf(r4.x, r4.z);
        den = r4.y * __expf(r4.x - M) + r4.w * __expf(r4.z - M);
        scl_hi = __expf(mhi - M) / den;
    }

    // phase 2 staging (overlays phase-1 planes; red/HmRaw untouched)
    uint32_t* sHmH = sm;
    uint32_t* sHmL = sm + PL;
    uint32_t* sAtH = sm + 2 * PL;
    uint32_t* sAtL = sm + 3 * PL;

    // attn -> [v][w] scalar bf16 hi/lo
    {
        __nv_bfloat16* pH = (__nv_bfloat16*)sAtH;
        __nv_bfloat16* pL = (__nv_bfloat16*)sAtL;
        const int wlo = mt * 16 + qr, whi = wlo + 8;
#pragma unroll
        for (int nj = 0; nj < 4; nj++) {
            const int v = nh * 32 + nj * 8 + 2 * qc;
#pragma unroll
            for (int r = 0; r < 4; r++) {
                float val = acc[nj][r] * ((r < 2) ? scl_lo : scl_hi);
                int vv = v + (r & 1);
                int ww = (r < 2) ? wlo : whi;
                __nv_bfloat16 h = __float2bfloat16_rn(val);
                pH[vv * (WS * 2) + ww] = h;
                pL[vv * (WS * 2) + ww] = __float2bfloat16_rn(val - __bfloat162float(h));
            }
        }
    }
    // Hm from the prefetched smem copy -> natural [h][w] hi/lo planes
    CP_WAIT0();
#pragma unroll
    for (int it = 0; it < 4; it++) {
        int i = tid * 4 + it * 1024;
        int off = (i >> 6) * WS + ((i & 63) >> 1);
        float4 v = *(const float4*)&HmRaw[i];
        uint32_t hA, lA, hB, lB;
        bfsplit2(v.x, v.y, hA, lA); bfsplit2(v.z, v.w, hB, lB);
        *(uint2*)&sHmH[off] = make_uint2(hA, hB);
        *(uint2*)&sHmL[off] = make_uint2(lA, lB);
    }
    __syncthreads();

    // GEMM2 (bf16x2): C[v][h] = sum_w attn[w][v] * Hm[h][w]  (= O^T), ldmatrix non-trans
#pragma unroll
    for (int nj = 0; nj < 4; nj++)
#pragma unroll
        for (int r = 0; r < 4; r++) acc[nj][r] = 0.f;

    const int mrowA2 = mt * 16 + (lane & 7) + 8 * ((lane >> 3) & 1);
    const int kcolA2 = 8 * ((lane >> 4) & 1);
    const int nrowB2 = nh * 32 + (lane & 7);
    const int kcolB2 = 8 * ((lane >> 3) & 1);
#pragma unroll
    for (int it = 0; it < 4; it++) {
        uint32_t aaddr = sb + 2 * PL * 4 + (mrowA2 * WS) * 4 + (it * 16 + kcolA2) * 2;
        uint32_t aH[4], aL[4];
        LDSM4N(aH[0], aH[1], aH[2], aH[3], aaddr);
        LDSM4N(aL[0], aL[1], aL[2], aL[3], aaddr + PL * 4);
#pragma unroll
        for (int nj = 0; nj < 4; nj++) {
            uint32_t baddr = sb + ((nrowB2 + nj * 8) * WS) * 4 + (it * 16 + kcolB2) * 2;
            uint32_t bH[2], bL[2];
            LDSM2N(bH[0], bH[1], baddr);
            LDSM2N(bL[0], bL[1], baddr + PL * 4);
            mma_bf16(acc[nj], aH, bH);
            mma_bf16(acc[nj], aH, bL);
            mma_bf16(acc[nj], aL, bH);
        }
    }

    // store O[h][v] (tf32-rounded for the final conv)
    float* O = o + (size_t)bc * HW;
    const int vr = mt * 16 + qr;
#pragma unroll
    for (int nj = 0; nj < 4; nj++) {
        const int hc = nh * 32 + nj * 8 + 2 * qc;
        O[hc * 64 + vr]           = rtf(acc[nj][0]);
        O[(hc + 1) * 64 + vr]     = rtf(acc[nj][1]);
        O[hc * 64 + vr + 8]       = rtf(acc[nj][2]);
        O[(hc + 1) * 64 + vr + 8] = rtf(acc[nj][3]);
    }
}

// ---------------------------------------------------------------------------
extern "C" void kernel_launch(void* const* d_in, const int* in_sizes, int n_in,
                              void* d_out, int out_size) {
    const float* x  = (const float*)d_in[0];
    const float* wf = (const float*)d_in[1];
    const float* bf = (const float*)d_in[2];
    const float* wg = (const float*)d_in[3];
    const float* bg = (const float*)d_in[4];
    const float* wh = (const float*)d_in[5];
    const float* bh = (const float*)d_in[6];
    const float* wv = (const float*)d_in[7];
    const float* bv = (const float*)d_in[8];

    float *yb, *ob, *xrF, *wtF, *wtvF, *bcat;
    cudaGetSymbolAddress((void**)&yb,   g_y);
    cudaGetSymbolAddress((void**)&ob,   g_o);
    cudaGetSymbolAddress((void**)&xrF,  g_xrF);
    cudaGetSymbolAddress((void**)&wtF,  g_wtF);
    cudaGetSymbolAddress((void**)&wtvF, g_wtvF);
    cudaGetSymbolAddress((void**)&bcat, g_bcat);

    cudaFuncSetAttribute(conv_mma_kernel<true>,
                         cudaFuncAttributeMaxDynamicSharedMemorySize, CONV_SMEM);
    cudaFuncSetAttribute(conv_mma_kernel<false>,
                         cudaFuncAttributeMaxDynamicSharedMemorySize, CONV_SMEM);
    cudaFuncSetAttribute(attn_kernel,
                         cudaFuncAttributeMaxDynamicSharedMemorySize, ATT_SMEM);

    // 1) weights -> fragment layout; x -> fragment layout (tf32-rounded)
    prep_w_kernel<<<256, 256>>>(wf, wg, wh, wv, bf, bg, bh);
    x_frag_kernel<<<32768, 256>>>(x);

    // 2) fused f/g/h conv
    conv_mma_kernel<true><<<dim3(32, 6, 16), 256, CONV_SMEM>>>(xrF, wtF, bcat, yb);

    // 3) per-(b,c) attention
    attn_kernel<<<4096, 256, ATT_SMEM>>>(yb, ob);

    // 4) output conv
    conv_mma_kernel<false><<<dim3(32, 2, 16), 256, CONV_SMEM>>>(ob, wtvF, bv, (float*)d_out);
}